// round 2
// baseline (speedup 1.0000x reference)
#include <cuda_runtime.h>
#include <stdint.h>
#include <math.h>

#define Bn 256
#define Nn 512
#define En 128
#define Hn 128
#define NEG_BIG (-100000000.0f)
#define TINY_F 1.17549435e-38f
#define FULLMASK 0xffffffffu

// out layout: [log_prob(256) | idxs(131072) | R(256) | start(512) | end(512)]
#define OUT_IDX   256
#define OUT_R     (OUT_IDX + Bn*Nn)
#define OUT_START (OUT_R + Bn)
#define OUT_END   (OUT_START + 2*Bn)

// ---------------- device scratch ----------------
__device__ float g_P[(size_t)Bn * Nn * Nn];     // 268 MB
__device__ float g_keys[(size_t)Bn * Nn * Hn];  // 67 MB
__device__ float g_ctxV[(size_t)Bn * Nn * En];  // 67 MB
__device__ float g_U[En * Hn];
__device__ float g_V[En * Hn];
__device__ float g_c0[Bn * Hn];
__device__ float g_q0[Bn * Hn];
__device__ float g_S0[Bn * Nn];
__device__ uint2 g_rng[Nn];

// ---------------- threefry2x32-20 (JAX-compatible) ----------------
__device__ __forceinline__ void tf2x32(uint32_t k0, uint32_t k1,
                                       uint32_t x0, uint32_t x1,
                                       uint32_t& y0, uint32_t& y1) {
    uint32_t k2 = k0 ^ k1 ^ 0x1BD11BDAu;
    x0 += k0; x1 += k1;
#define TF_RND(R) { x0 += x1; x1 = __funnelshift_l(x1, x1, (R)); x1 ^= x0; }
    TF_RND(13) TF_RND(15) TF_RND(26) TF_RND(6)   x0 += k1; x1 += k2 + 1u;
    TF_RND(17) TF_RND(29) TF_RND(16) TF_RND(24)  x0 += k2; x1 += k0 + 2u;
    TF_RND(13) TF_RND(15) TF_RND(26) TF_RND(6)   x0 += k0; x1 += k1 + 3u;
    TF_RND(17) TF_RND(29) TF_RND(16) TF_RND(24)  x0 += k1; x1 += k2 + 4u;
    TF_RND(13) TF_RND(15) TF_RND(26) TF_RND(6)   x0 += k2; x1 += k0 + 5u;
#undef TF_RND
    y0 = x0; y1 = x1;
}

__device__ __forceinline__ float gumbel_for(int step, uint32_t c) {
    uint2 k = g_rng[step];
    uint32_t y0, y1;
    tf2x32(k.x, k.y, 0u, c, y0, y1);           // partitionable: counts = (hi=0, lo=c)
    uint32_t bits = y0 ^ y1;
    float f = __uint_as_float((bits >> 9) | 0x3f800000u) - 1.0f;
    float u = (f == 0.0f) ? TINY_F : f;        // uniform(tiny, 1)
    return -logf(-logf(u));
}

// ---------------- precompute kernels ----------------
__global__ void k_rng() {
    int i = threadIdx.x;  // 512
    uint32_t y0, y1;
    tf2x32(0u, 42u, 0u, (uint32_t)i, y0, y1);  // foldlike split of key(42)
    g_rng[i] = make_uint2(y0, y1);
}

__global__ void k_uv(const float* __restrict__ W_v, const float* __restrict__ W_q) {
    int i = blockIdx.x;   // 0..127
    int h = threadIdx.x;  // 0..127
    float u = 0.f, v = 0.f;
    for (int j = 0; j < En; j++) {
        float wq = W_q[j * Hn + h];
        u += W_v[i * En + j] * wq;
        v += W_v[(En + i) * En + j] * wq;
    }
    g_U[i * Hn + h] = u;
    g_V[i * Hn + h] = v;
}

__global__ void k_rowconst(const float* __restrict__ ctx, const float* __restrict__ liw,
                           const float* __restrict__ W_h, const float* __restrict__ b_h,
                           const float* __restrict__ W_v, const float* __restrict__ b_v,
                           const float* __restrict__ W_q, const float* __restrict__ b_q) {
    __shared__ float mean_s[En];
    __shared__ float hbv[En];
    __shared__ float w0[En];
    int b = blockIdx.x, t = threadIdx.x;  // 128 threads
    double acc = 0.0;
    for (int n = 0; n < Nn; n++) acc += (double)ctx[((size_t)b * Nn + n) * En + t];
    mean_s[t] = (float)(acc * (1.0 / 512.0));
    float a2 = 0.f;
    for (int e2 = 0; e2 < 2 * En; e2++) a2 += liw[e2] * W_v[e2 * En + t];
    w0[t] = a2;
    __syncthreads();
    float hb = b_h[t];
    for (int e = 0; e < En; e++) hb += mean_s[e] * W_h[e * En + t];
    hbv[t] = hb + b_v[t];
    __syncthreads();
    float c0 = b_q[t], qw = 0.f;
    for (int e = 0; e < En; e++) {
        float wq = W_q[e * Hn + t];
        c0 += hbv[e] * wq;
        qw += w0[e] * wq;
    }
    g_c0[b * Hn + t] = c0;
    g_q0[b * Hn + t] = c0 + qw;
}

// C[b, rt*128+r, c] = A[b, rt*128+r, :] @ Bm[:, c] (+ bias)
template <bool HASBIAS>
__global__ void k_gemm_nn(const float* __restrict__ A, const float* __restrict__ Bm,
                          const float* __restrict__ bias, float* __restrict__ C) {
    extern __shared__ float sm[];
    float* Ast = sm;               // [128][132] transposed: Ast[k][r]
    float* Bs  = sm + 128 * 132;   // [128][128]: Bs[k][c]
    int b = blockIdx.y, rt = blockIdx.x;
    const float* Ab = A + ((size_t)b * Nn + rt * 128) * En;
    int t = threadIdx.x;           // 256
    for (int f = t; f < 128 * 128; f += 256) {
        int r = f >> 7, k = f & 127;
        Ast[k * 132 + r] = Ab[r * En + k];
    }
    for (int f = t; f < 128 * 128; f += 256) {
        int k = f >> 7, c = f & 127;
        Bs[k * 128 + c] = Bm[k * Hn + c];
    }
    __syncthreads();
    int tr = (t >> 4) * 8, tc = (t & 15) * 8;
    float acc[8][8];
#pragma unroll
    for (int i = 0; i < 8; i++)
#pragma unroll
        for (int j = 0; j < 8; j++) acc[i][j] = 0.f;
    for (int k = 0; k < 128; k++) {
        float a[8], bb[8];
#pragma unroll
        for (int i = 0; i < 8; i++) a[i] = Ast[k * 132 + tr + i];
#pragma unroll
        for (int j = 0; j < 8; j++) bb[j] = Bs[k * 128 + tc + j];
#pragma unroll
        for (int i = 0; i < 8; i++)
#pragma unroll
            for (int j = 0; j < 8; j++) acc[i][j] += a[i] * bb[j];
    }
    float* Cb = C + ((size_t)b * Nn + rt * 128) * Hn;
#pragma unroll
    for (int i = 0; i < 8; i++)
#pragma unroll
        for (int j = 0; j < 8; j++) {
            float v = acc[i][j];
            if (HASBIAS) v += bias[tc + j];
            Cb[(tr + i) * Hn + tc + j] = v;
        }
}

// P[b, rt*128+r, ct*128+c] = scale * ctxV[b, rt*128+r, :] . keys[b, ct*128+c, :]
__global__ void k_gemm_nt() {
    extern __shared__ float sm[];
    float* Ast = sm;               // [128][132]
    float* Bst = sm + 128 * 132;   // [128][132]
    int b = blockIdx.z, rt = blockIdx.y, ct = blockIdx.x;
    const float scale = 1.0f / sqrtf(128.0f);
    const float* Ab = g_ctxV + ((size_t)b * Nn + rt * 128) * En;
    const float* Bb = g_keys + ((size_t)b * Nn + ct * 128) * Hn;
    int t = threadIdx.x;
    for (int f = t; f < 128 * 128; f += 256) {
        int r = f >> 7, k = f & 127;
        Ast[k * 132 + r] = Ab[r * En + k];
    }
    for (int f = t; f < 128 * 128; f += 256) {
        int r = f >> 7, k = f & 127;
        Bst[k * 132 + r] = Bb[r * Hn + k];
    }
    __syncthreads();
    int tr = (t >> 4) * 8, tc = (t & 15) * 8;
    float acc[8][8];
#pragma unroll
    for (int i = 0; i < 8; i++)
#pragma unroll
        for (int j = 0; j < 8; j++) acc[i][j] = 0.f;
    for (int k = 0; k < 128; k++) {
        float a[8], bb[8];
#pragma unroll
        for (int i = 0; i < 8; i++) a[i] = Ast[k * 132 + tr + i];
#pragma unroll
        for (int j = 0; j < 8; j++) bb[j] = Bst[k * 132 + tc + j];
#pragma unroll
        for (int i = 0; i < 8; i++)
#pragma unroll
            for (int j = 0; j < 8; j++) acc[i][j] += a[i] * bb[j];
    }
    float* Cb = g_P + (size_t)b * Nn * Nn;
#pragma unroll
    for (int i = 0; i < 8; i++)
#pragma unroll
        for (int j = 0; j < 8; j++)
            Cb[(size_t)(rt * 128 + tr + i) * Nn + (ct * 128 + tc + j)] = scale * acc[i][j];
}

// S0[b,n] = scale * q0[b] . keys[b,n]
__global__ void k_s0() {
    __shared__ float sq0[Hn];
    int b = blockIdx.x, tid = threadIdx.x;  // 512
    if (tid < Hn) sq0[tid] = g_q0[b * Hn + tid];
    __syncthreads();
    const float scale = 1.0f / sqrtf(128.0f);
    const float4* kr = (const float4*)&g_keys[((size_t)b * Nn + tid) * Hn];
    float d = 0.f;
#pragma unroll 8
    for (int h4 = 0; h4 < 32; h4++) {
        float4 kv = kr[h4];
        d += sq0[4 * h4] * kv.x + sq0[4 * h4 + 1] * kv.y +
             sq0[4 * h4 + 2] * kv.z + sq0[4 * h4 + 3] * kv.w;
    }
    g_S0[b * Nn + tid] = scale * d;
}

// ---------------- sequential decoder: 1 block per batch row ----------------
__global__ __launch_bounds__(512, 2)
void k_decode(const float* __restrict__ ctx, const float* __restrict__ orig,
              const float* __restrict__ mask_in, float* __restrict__ out) {
    __shared__ float s_row[En];    // ctx[idx0] then cu = c0+u
    __shared__ float s_u[En];
    __shared__ float rK[16]; __shared__ int rI[16]; __shared__ float rM[16];
    __shared__ float rS[16];
    __shared__ float sSel; __shared__ int sIdxSh; __shared__ float sMaxSh;

    int b = blockIdx.x, tid = threadIdx.x;  // 512 threads, tid == n
    const float scale = 1.0f / sqrtf(128.0f);
    bool masked = mask_in[b * Nn + tid] > 0.0f;
    float c0r = 0.f;                         // scale*( (c0+u) . k_n ), set after step 0
    float logp_acc = 0.f, Racc = 0.f, px = 0.f, py = 0.f;
    float s = g_S0[b * Nn + tid];
    float g = gumbel_for(0, (uint32_t)(b * Nn + tid));
    float Pnext = 0.f;

    for (int i = 0; i < Nn; i++) {
        float sp = masked ? NEG_BIG : 10.0f * tanhf(s);
        float key = sp + g;
        // reduction 1: argmax(key) (first-index ties) + max(sp)
        float kk = key; int id = tid; float m = sp;
#pragma unroll
        for (int off = 16; off; off >>= 1) {
            float k2 = __shfl_down_sync(FULLMASK, kk, off);
            int  i2 = __shfl_down_sync(FULLMASK, id, off);
            float m2 = __shfl_down_sync(FULLMASK, m, off);
            if (k2 > kk) { kk = k2; id = i2; }
            m = fmaxf(m, m2);
        }
        int wid = tid >> 5;
        if ((tid & 31) == 0) { rK[wid] = kk; rI[wid] = id; rM[wid] = m; }
        __syncthreads();
        if (tid < 32) {
            float k1_ = (tid < 16) ? rK[tid] : -INFINITY;
            int  i1_ = (tid < 16) ? rI[tid] : 0;
            float m1_ = (tid < 16) ? rM[tid] : -INFINITY;
#pragma unroll
            for (int off = 8; off; off >>= 1) {
                float k2 = __shfl_down_sync(FULLMASK, k1_, off);
                int  i2 = __shfl_down_sync(FULLMASK, i1_, off);
                float m2 = __shfl_down_sync(FULLMASK, m1_, off);
                if (k2 > k1_) { k1_ = k2; i1_ = i2; }
                m1_ = fmaxf(m1_, m2);
            }
            if (tid == 0) { sIdxSh = i1_; sMaxSh = m1_; }
        }
        __syncthreads();
        int idx = sIdxSh; float smax = sMaxSh;
        if (tid == idx) { sSel = sp; masked = true; }
        // prefetch next P row + gumbel while reduction 2 runs
        if (i + 1 < Nn) {
            Pnext = g_P[((size_t)b * Nn + idx) * (size_t)Nn + tid];
            g = gumbel_for(i + 1, (uint32_t)(b * Nn + tid));
        }
        if (tid == 0) {
            out[OUT_IDX + b * Nn + i] = (float)idx;
            float ox = orig[((size_t)b * Nn + idx) * 2];
            float oy = orig[((size_t)b * Nn + idx) * 2 + 1];
            if (i > 0) { float dx = ox - px, dy = oy - py; Racc += sqrtf(dx * dx + dy * dy); }
            px = ox; py = oy;
            if (i == 0) { out[OUT_START + 2 * b] = ox; out[OUT_START + 2 * b + 1] = oy; }
            if (i == Nn - 1) {
                out[OUT_END + 2 * b] = ox; out[OUT_END + 2 * b + 1] = oy;
                out[OUT_R + b] = Racc;
            }
        }
        // reduction 2: sum exp(sp - smax)  -> logp
        float e = expf(sp - smax);
#pragma unroll
        for (int off = 16; off; off >>= 1) e += __shfl_down_sync(FULLMASK, e, off);
        if ((tid & 31) == 0) rS[wid] = e;
        __syncthreads();
        if (tid == 0) {
            float se = 0.f;
#pragma unroll
            for (int w = 0; w < 16; w++) se += rS[w];
            logp_acc += sSel - (smax + logf(se));
            if (i == Nn - 1) out[b] = logp_acc;
        }
        // step 0 only: build cu = c0 + ctx[idx0]@U, then c0r = scale*(cu . k_n)
        if (i == 0) {
            if (tid < En) s_row[tid] = ctx[((size_t)b * Nn + idx) * En + tid];
            __syncthreads();
            if (tid < En) {
                float uu = 0.f;
                for (int e2 = 0; e2 < En; e2++) uu += s_row[e2] * g_U[e2 * Hn + tid];
                s_u[tid] = uu + g_c0[b * Hn + tid];
            }
            __syncthreads();
            const float4* kr = (const float4*)&g_keys[((size_t)b * Nn + tid) * Hn];
            float qd = 0.f;
#pragma unroll 8
            for (int h4 = 0; h4 < 32; h4++) {
                float4 kv = kr[h4];
                qd += s_u[4 * h4] * kv.x + s_u[4 * h4 + 1] * kv.y +
                      s_u[4 * h4 + 2] * kv.z + s_u[4 * h4 + 3] * kv.w;
            }
            c0r = scale * qd;
        }
        __syncthreads();           // protect shared reuse next iteration
        s = c0r + Pnext;
    }
}

// ---------------- launch ----------------
extern "C" void kernel_launch(void* const* d_in, const int* in_sizes, int n_in,
                              void* d_out, int out_size) {
    const float* ctx   = (const float*)d_in[0];
    const float* orig  = (const float*)d_in[1];
    const float* maskp = (const float*)d_in[2];
    const float* liw   = (const float*)d_in[3];
    const float* W_h   = (const float*)d_in[4];
    const float* b_h   = (const float*)d_in[5];
    const float* W_v   = (const float*)d_in[6];
    const float* b_v   = (const float*)d_in[7];
    const float* W_q   = (const float*)d_in[8];
    const float* b_q   = (const float*)d_in[9];
    const float* W_k   = (const float*)d_in[10];
    const float* b_k   = (const float*)d_in[11];
    float* out = (float*)d_out;

    void *pV, *pCtxV, *pKeys;
    cudaGetSymbolAddress(&pV, g_V);
    cudaGetSymbolAddress(&pCtxV, g_ctxV);
    cudaGetSymbolAddress(&pKeys, g_keys);

    const int NN_SMEM = (128 * 132 + 128 * 128) * 4;
    const int NT_SMEM = (2 * 128 * 132) * 4;
    cudaFuncSetAttribute(k_gemm_nn<false>, cudaFuncAttributeMaxDynamicSharedMemorySize, NN_SMEM);
    cudaFuncSetAttribute(k_gemm_nn<true>,  cudaFuncAttributeMaxDynamicSharedMemorySize, NN_SMEM);
    cudaFuncSetAttribute(k_gemm_nt,        cudaFuncAttributeMaxDynamicSharedMemorySize, NT_SMEM);

    k_rng<<<1, 512>>>();
    k_uv<<<128, 128>>>(W_v, W_q);
    k_rowconst<<<256, 128>>>(ctx, liw, W_h, b_h, W_v, b_v, W_q, b_q);
    k_gemm_nn<false><<<dim3(4, 256), 256, NN_SMEM>>>(ctx, (const float*)pV, nullptr, (float*)pCtxV);
    k_gemm_nn<true><<<dim3(4, 256), 256, NN_SMEM>>>(ctx, W_k, b_k, (float*)pKeys);
    k_gemm_nt<<<dim3(4, 4, 256), 256, NT_SMEM>>>();
    k_s0<<<256, 512>>>();
    k_decode<<<256, 512>>>(ctx, orig, maskp, out);
}

// round 3
// speedup vs baseline: 1.1756x; 1.1756x over previous
#include <cuda_runtime.h>
#include <stdint.h>
#include <math.h>

#define Bn 256
#define Nn 512
#define En 128
#define Hn 128
#define NEG_BIG (-100000000.0f)
#define TINY_F 1.17549435e-38f
#define FULLMASK 0xffffffffu

// out layout: [log_prob(256) | idxs(131072) | R(256) | start(512) | end(512)]
#define OUT_IDX   256
#define OUT_R     (OUT_IDX + Bn*Nn)
#define OUT_START (OUT_R + Bn)
#define OUT_END   (OUT_START + 2*Bn)

// ---------------- device scratch ----------------
__device__ float g_P[(size_t)Bn * Nn * Nn];     // 268 MB
__device__ float g_keys[(size_t)Bn * Nn * Hn];  // 67 MB
__device__ float g_ctxV[(size_t)Bn * Nn * En];  // 67 MB
__device__ float g_U[En * Hn];
__device__ float g_V[En * Hn];
__device__ float g_c0[Bn * Hn];
__device__ float g_q0[Bn * Hn];
__device__ float g_S0[Bn * Nn];
__device__ uint2 g_rng[Nn];

// ---------------- threefry2x32-20 (JAX-compatible) ----------------
__device__ __forceinline__ void tf2x32(uint32_t k0, uint32_t k1,
                                       uint32_t x0, uint32_t x1,
                                       uint32_t& y0, uint32_t& y1) {
    uint32_t k2 = k0 ^ k1 ^ 0x1BD11BDAu;
    x0 += k0; x1 += k1;
#define TF_RND(R) { x0 += x1; x1 = __funnelshift_l(x1, x1, (R)); x1 ^= x0; }
    TF_RND(13) TF_RND(15) TF_RND(26) TF_RND(6)   x0 += k1; x1 += k2 + 1u;
    TF_RND(17) TF_RND(29) TF_RND(16) TF_RND(24)  x0 += k2; x1 += k0 + 2u;
    TF_RND(13) TF_RND(15) TF_RND(26) TF_RND(6)   x0 += k0; x1 += k1 + 3u;
    TF_RND(17) TF_RND(29) TF_RND(16) TF_RND(24)  x0 += k1; x1 += k2 + 4u;
    TF_RND(13) TF_RND(15) TF_RND(26) TF_RND(6)   x0 += k2; x1 += k0 + 5u;
#undef TF_RND
    y0 = x0; y1 = x1;
}

__device__ __forceinline__ float gumbel_for(int step, uint32_t c) {
    uint2 k = g_rng[step];
    uint32_t y0, y1;
    tf2x32(k.x, k.y, 0u, c, y0, y1);
    uint32_t bits = y0 ^ y1;
    float f = __uint_as_float((bits >> 9) | 0x3f800000u) - 1.0f;
    float u = (f == 0.0f) ? TINY_F : f;
    return -logf(-logf(u));
}

// ---------------- precompute kernels ----------------
__global__ void k_rng() {
    int i = threadIdx.x;  // 512
    uint32_t y0, y1;
    tf2x32(0u, 42u, 0u, (uint32_t)i, y0, y1);
    g_rng[i] = make_uint2(y0, y1);
}

__global__ void k_uv(const float* __restrict__ W_v, const float* __restrict__ W_q) {
    int i = blockIdx.x;
    int h = threadIdx.x;
    float u = 0.f, v = 0.f;
    for (int j = 0; j < En; j++) {
        float wq = W_q[j * Hn + h];
        u += W_v[i * En + j] * wq;
        v += W_v[(En + i) * En + j] * wq;
    }
    g_U[i * Hn + h] = u;
    g_V[i * Hn + h] = v;
}

__global__ void k_rowconst(const float* __restrict__ ctx, const float* __restrict__ liw,
                           const float* __restrict__ W_h, const float* __restrict__ b_h,
                           const float* __restrict__ W_v, const float* __restrict__ b_v,
                           const float* __restrict__ W_q, const float* __restrict__ b_q) {
    __shared__ float mean_s[En];
    __shared__ float hbv[En];
    __shared__ float w0[En];
    int b = blockIdx.x, t = threadIdx.x;  // 128 threads
    double acc = 0.0;
    for (int n = 0; n < Nn; n++) acc += (double)ctx[((size_t)b * Nn + n) * En + t];
    mean_s[t] = (float)(acc * (1.0 / 512.0));
    float a2 = 0.f;
    for (int e2 = 0; e2 < 2 * En; e2++) a2 += liw[e2] * W_v[e2 * En + t];
    w0[t] = a2;
    __syncthreads();
    float hb = b_h[t];
    for (int e = 0; e < En; e++) hb += mean_s[e] * W_h[e * En + t];
    hbv[t] = hb + b_v[t];
    __syncthreads();
    float c0 = b_q[t], qw = 0.f;
    for (int e = 0; e < En; e++) {
        float wq = W_q[e * Hn + t];
        c0 += hbv[e] * wq;
        qw += w0[e] * wq;
    }
    g_c0[b * Hn + t] = c0;
    g_q0[b * Hn + t] = c0 + qw;
}

// ============ K-chunked double-buffered GEMMs (2 CTAs/SM) ============
// NN: C[b, rt*128+r, c] = ctx[b, rt*128+r, :] @ Bm (+bias). grid (4, 256, 2)
__global__ __launch_bounds__(256, 2)
void k_gemm_nn2(const float* __restrict__ A, const float* __restrict__ B0,
                const float* __restrict__ B1, const float* __restrict__ bias1,
                float* __restrict__ C0, float* __restrict__ C1) {
    extern __shared__ float sm[];
    float* Abuf0 = sm;                    // [32][132]
    float* Abuf1 = sm + 32 * 132;
    float* Bbuf0 = sm + 2 * 32 * 132;     // [32][128]
    float* Bbuf1 = Bbuf0 + 32 * 128;
    int rt = blockIdx.x, b = blockIdx.y, which = blockIdx.z;
    const float* Bm   = which ? B1 : B0;
    const float* bias = which ? bias1 : nullptr;
    float*       C    = which ? C1 : C0;
    const float* Ab = A + ((size_t)b * Nn + rt * 128) * En;
    int t = threadIdx.x;
    int tr = (t >> 4) * 8, tc = (t & 15) * 8;

    float4 ra[4], rb[4];
#define LDG_CHUNK(K0)                                                          \
    _Pragma("unroll") for (int s = 0; s < 4; s++) {                            \
        int f = t + 256 * s; int r = f >> 3, kq = f & 7;                       \
        ra[s] = *(const float4*)&Ab[r * En + (K0) + kq * 4];                   \
    }                                                                          \
    _Pragma("unroll") for (int s = 0; s < 4; s++) {                            \
        int f = t + 256 * s; int k = f >> 5, cq = f & 31;                      \
        rb[s] = *(const float4*)&Bm[(size_t)((K0) + k) * Hn + cq * 4];         \
    }
#define STS_CHUNK(AB, BB)                                                      \
    _Pragma("unroll") for (int s = 0; s < 4; s++) {                            \
        int f = t + 256 * s; int r = f >> 3, kq = f & 7;                       \
        (AB)[(kq * 4 + 0) * 132 + r] = ra[s].x;                                \
        (AB)[(kq * 4 + 1) * 132 + r] = ra[s].y;                                \
        (AB)[(kq * 4 + 2) * 132 + r] = ra[s].z;                                \
        (AB)[(kq * 4 + 3) * 132 + r] = ra[s].w;                                \
    }                                                                          \
    _Pragma("unroll") for (int s = 0; s < 4; s++) {                            \
        *(float4*)&(BB)[(t + 256 * s) * 4] = rb[s];                            \
    }

    float acc[8][8];
#pragma unroll
    for (int i = 0; i < 8; i++)
#pragma unroll
        for (int j = 0; j < 8; j++) acc[i][j] = 0.f;

    LDG_CHUNK(0)
    STS_CHUNK(Abuf0, Bbuf0)
    __syncthreads();
#pragma unroll
    for (int ch = 0; ch < 4; ch++) {
        if (ch < 3) { LDG_CHUNK((ch + 1) * 32) }
        const float* Ac = (ch & 1) ? Abuf1 : Abuf0;
        const float* Bc = (ch & 1) ? Bbuf1 : Bbuf0;
#pragma unroll
        for (int k = 0; k < 32; k++) {
            float a[8], bb[8];
#pragma unroll
            for (int i = 0; i < 8; i++) a[i] = Ac[k * 132 + tr + i];
#pragma unroll
            for (int j = 0; j < 8; j++) bb[j] = Bc[k * 128 + tc + j];
#pragma unroll
            for (int i = 0; i < 8; i++)
#pragma unroll
                for (int j = 0; j < 8; j++) acc[i][j] += a[i] * bb[j];
        }
        if (ch < 3) {
            float* An = (ch & 1) ? Abuf0 : Abuf1;
            float* Bnx = (ch & 1) ? Bbuf0 : Bbuf1;
            STS_CHUNK(An, Bnx)
            __syncthreads();
        }
    }
    float* Cb = C + ((size_t)b * Nn + rt * 128) * Hn;
#pragma unroll
    for (int i = 0; i < 8; i++)
#pragma unroll
        for (int j = 0; j < 8; j++) {
            float v = acc[i][j];
            if (bias) v += bias[tc + j];
            Cb[(tr + i) * Hn + tc + j] = v;
        }
#undef LDG_CHUNK
#undef STS_CHUNK
}

// NT: P[b, rt*128+r, ct*128+c] = scale * ctxV[b,r,:] . keys[b,c,:]. grid (4, 4, 256)
__global__ __launch_bounds__(256, 2)
void k_gemm_nt2() {
    extern __shared__ float sm[];
    float* Abuf0 = sm;                    // [32][132]
    float* Abuf1 = sm + 32 * 132;
    float* Bbuf0 = sm + 2 * 32 * 132;     // [32][132]
    float* Bbuf1 = Bbuf0 + 32 * 132;
    int ct = blockIdx.x, rt = blockIdx.y, b = blockIdx.z;
    const float scale = 1.0f / sqrtf(128.0f);
    const float* Ab = g_ctxV + ((size_t)b * Nn + rt * 128) * En;
    const float* Bb = g_keys + ((size_t)b * Nn + ct * 128) * Hn;
    int t = threadIdx.x;
    int tr = (t >> 4) * 8, tc = (t & 15) * 8;

    float4 ra[4], rb[4];
#define LDG_CHUNK(K0)                                                          \
    _Pragma("unroll") for (int s = 0; s < 4; s++) {                            \
        int f = t + 256 * s; int r = f >> 3, kq = f & 7;                       \
        ra[s] = *(const float4*)&Ab[r * En + (K0) + kq * 4];                   \
        rb[s] = *(const float4*)&Bb[r * Hn + (K0) + kq * 4];                   \
    }
#define STS_CHUNK(AB, BB)                                                      \
    _Pragma("unroll") for (int s = 0; s < 4; s++) {                            \
        int f = t + 256 * s; int r = f >> 3, kq = f & 7;                       \
        (AB)[(kq * 4 + 0) * 132 + r] = ra[s].x;                                \
        (AB)[(kq * 4 + 1) * 132 + r] = ra[s].y;                                \
        (AB)[(kq * 4 + 2) * 132 + r] = ra[s].z;                                \
        (AB)[(kq * 4 + 3) * 132 + r] = ra[s].w;                                \
        (BB)[(kq * 4 + 0) * 132 + r] = rb[s].x;                                \
        (BB)[(kq * 4 + 1) * 132 + r] = rb[s].y;                                \
        (BB)[(kq * 4 + 2) * 132 + r] = rb[s].z;                                \
        (BB)[(kq * 4 + 3) * 132 + r] = rb[s].w;                                \
    }

    float acc[8][8];
#pragma unroll
    for (int i = 0; i < 8; i++)
#pragma unroll
        for (int j = 0; j < 8; j++) acc[i][j] = 0.f;

    LDG_CHUNK(0)
    STS_CHUNK(Abuf0, Bbuf0)
    __syncthreads();
#pragma unroll
    for (int ch = 0; ch < 4; ch++) {
        if (ch < 3) { LDG_CHUNK((ch + 1) * 32) }
        const float* Ac = (ch & 1) ? Abuf1 : Abuf0;
        const float* Bc = (ch & 1) ? Bbuf1 : Bbuf0;
#pragma unroll
        for (int k = 0; k < 32; k++) {
            float a[8], bb[8];
#pragma unroll
            for (int i = 0; i < 8; i++) a[i] = Ac[k * 132 + tr + i];
#pragma unroll
            for (int j = 0; j < 8; j++) bb[j] = Bc[k * 132 + tc + j];
#pragma unroll
            for (int i = 0; i < 8; i++)
#pragma unroll
                for (int j = 0; j < 8; j++) acc[i][j] += a[i] * bb[j];
        }
        if (ch < 3) {
            float* An = (ch & 1) ? Abuf0 : Abuf1;
            float* Bnx = (ch & 1) ? Bbuf0 : Bbuf1;
            STS_CHUNK(An, Bnx)
            __syncthreads();
        }
    }
    float* Cb = g_P + (size_t)b * Nn * Nn;
#pragma unroll
    for (int i = 0; i < 8; i++)
#pragma unroll
        for (int j = 0; j < 8; j++)
            Cb[(size_t)(rt * 128 + tr + i) * Nn + (ct * 128 + tc + j)] = scale * acc[i][j];
#undef LDG_CHUNK
#undef STS_CHUNK
}

// S0[b,n] = scale * q0[b] . keys[b,n]
__global__ void k_s0() {
    __shared__ float sq0[Hn];
    int b = blockIdx.x, tid = threadIdx.x;  // 512
    if (tid < Hn) sq0[tid] = g_q0[b * Hn + tid];
    __syncthreads();
    const float scale = 1.0f / sqrtf(128.0f);
    const float4* kr = (const float4*)&g_keys[((size_t)b * Nn + tid) * Hn];
    float d = 0.f;
#pragma unroll 8
    for (int h4 = 0; h4 < 32; h4++) {
        float4 kv = kr[h4];
        d += sq0[4 * h4] * kv.x + sq0[4 * h4 + 1] * kv.y +
             sq0[4 * h4 + 2] * kv.z + sq0[4 * h4 + 3] * kv.w;
    }
    g_S0[b * Nn + tid] = scale * d;
}

// ---------------- sequential decoder: 1 block per batch row ----------------
__global__ __launch_bounds__(512, 2)
void k_decode(const float* __restrict__ ctx, const float* __restrict__ orig,
              const float* __restrict__ mask_in, float* __restrict__ out) {
    __shared__ float s_row[En];
    __shared__ float s_u[En];
    __shared__ float rK[16]; __shared__ int rI[16]; __shared__ float rM[16];
    __shared__ float rS[16];
    __shared__ float sSel; __shared__ int sIdxSh; __shared__ float sMaxSh;

    int b = blockIdx.x, tid = threadIdx.x;
    const float scale = 1.0f / sqrtf(128.0f);
    bool masked = mask_in[b * Nn + tid] > 0.0f;
    float c0r = 0.f;
    float logp_acc = 0.f, Racc = 0.f, px = 0.f, py = 0.f;
    float s = g_S0[b * Nn + tid];
    float g = gumbel_for(0, (uint32_t)(b * Nn + tid));
    float Pnext = 0.f;

    for (int i = 0; i < Nn; i++) {
        float sp = masked ? NEG_BIG : 10.0f * tanhf(s);
        float key = sp + g;
        float kk = key; int id = tid; float m = sp;
#pragma unroll
        for (int off = 16; off; off >>= 1) {
            float k2 = __shfl_down_sync(FULLMASK, kk, off);
            int  i2 = __shfl_down_sync(FULLMASK, id, off);
            float m2 = __shfl_down_sync(FULLMASK, m, off);
            if (k2 > kk) { kk = k2; id = i2; }
            m = fmaxf(m, m2);
        }
        int wid = tid >> 5;
        if ((tid & 31) == 0) { rK[wid] = kk; rI[wid] = id; rM[wid] = m; }
        __syncthreads();
        if (tid < 32) {
            float k1_ = (tid < 16) ? rK[tid] : -INFINITY;
            int  i1_ = (tid < 16) ? rI[tid] : 0;
            float m1_ = (tid < 16) ? rM[tid] : -INFINITY;
#pragma unroll
            for (int off = 8; off; off >>= 1) {
                float k2 = __shfl_down_sync(FULLMASK, k1_, off);
                int  i2 = __shfl_down_sync(FULLMASK, i1_, off);
                float m2 = __shfl_down_sync(FULLMASK, m1_, off);
                if (k2 > k1_) { k1_ = k2; i1_ = i2; }
                m1_ = fmaxf(m1_, m2);
            }
            if (tid == 0) { sIdxSh = i1_; sMaxSh = m1_; }
        }
        __syncthreads();
        int idx = sIdxSh; float smax = sMaxSh;
        if (tid == idx) { sSel = sp; masked = true; }
        if (i + 1 < Nn) {
            Pnext = g_P[((size_t)b * Nn + idx) * (size_t)Nn + tid];
            g = gumbel_for(i + 1, (uint32_t)(b * Nn + tid));
        }
        if (tid == 0) {
            out[OUT_IDX + b * Nn + i] = (float)idx;
            float ox = orig[((size_t)b * Nn + idx) * 2];
            float oy = orig[((size_t)b * Nn + idx) * 2 + 1];
            if (i > 0) { float dx = ox - px, dy = oy - py; Racc += sqrtf(dx * dx + dy * dy); }
            px = ox; py = oy;
            if (i == 0) { out[OUT_START + 2 * b] = ox; out[OUT_START + 2 * b + 1] = oy; }
            if (i == Nn - 1) {
                out[OUT_END + 2 * b] = ox; out[OUT_END + 2 * b + 1] = oy;
                out[OUT_R + b] = Racc;
            }
        }
        float e = expf(sp - smax);
#pragma unroll
        for (int off = 16; off; off >>= 1) e += __shfl_down_sync(FULLMASK, e, off);
        if ((tid & 31) == 0) rS[wid] = e;
        __syncthreads();
        if (tid == 0) {
            float se = 0.f;
#pragma unroll
            for (int w = 0; w < 16; w++) se += rS[w];
            logp_acc += sSel - (smax + logf(se));
            if (i == Nn - 1) out[b] = logp_acc;
        }
        if (i == 0) {
            if (tid < En) s_row[tid] = ctx[((size_t)b * Nn + idx) * En + tid];
            __syncthreads();
            if (tid < En) {
                float uu = 0.f;
                for (int e2 = 0; e2 < En; e2++) uu += s_row[e2] * g_U[e2 * Hn + tid];
                s_u[tid] = uu + g_c0[b * Hn + tid];
            }
            __syncthreads();
            const float4* kr = (const float4*)&g_keys[((size_t)b * Nn + tid) * Hn];
            float qd = 0.f;
#pragma unroll 8
            for (int h4 = 0; h4 < 32; h4++) {
                float4 kv = kr[h4];
                qd += s_u[4 * h4] * kv.x + s_u[4 * h4 + 1] * kv.y +
                      s_u[4 * h4 + 2] * kv.z + s_u[4 * h4 + 3] * kv.w;
            }
            c0r = scale * qd;
        }
        __syncthreads();
        s = c0r + Pnext;
    }
}

// ---------------- launch ----------------
extern "C" void kernel_launch(void* const* d_in, const int* in_sizes, int n_in,
                              void* d_out, int out_size) {
    const float* ctx   = (const float*)d_in[0];
    const float* orig  = (const float*)d_in[1];
    const float* maskp = (const float*)d_in[2];
    const float* liw   = (const float*)d_in[3];
    const float* W_h   = (const float*)d_in[4];
    const float* b_h   = (const float*)d_in[5];
    const float* W_v   = (const float*)d_in[6];
    const float* b_v   = (const float*)d_in[7];
    const float* W_q   = (const float*)d_in[8];
    const float* b_q   = (const float*)d_in[9];
    const float* W_k   = (const float*)d_in[10];
    const float* b_k   = (const float*)d_in[11];
    float* out = (float*)d_out;

    void *pV, *pCtxV, *pKeys;
    cudaGetSymbolAddress(&pV, g_V);
    cudaGetSymbolAddress(&pCtxV, g_ctxV);
    cudaGetSymbolAddress(&pKeys, g_keys);

    const int NN_SMEM = (2 * 32 * 132 + 2 * 32 * 128) * 4;   // 66.5 KB
    const int NT_SMEM = (4 * 32 * 132) * 4;                  // 67.6 KB
    cudaFuncSetAttribute(k_gemm_nn2, cudaFuncAttributeMaxDynamicSharedMemorySize, NN_SMEM);
    cudaFuncSetAttribute(k_gemm_nt2, cudaFuncAttributeMaxDynamicSharedMemorySize, NT_SMEM);

    k_rng<<<1, 512>>>();
    k_uv<<<128, 128>>>(W_v, W_q);
    k_rowconst<<<256, 128>>>(ctx, liw, W_h, b_h, W_v, b_v, W_q, b_q);
    k_gemm_nn2<<<dim3(4, Bn, 2), 256, NN_SMEM>>>(ctx, (const float*)pV, W_k, b_k,
                                                 (float*)pCtxV, (float*)pKeys);
    k_gemm_nt2<<<dim3(4, 4, Bn), 256, NT_SMEM>>>();
    k_s0<<<256, 512>>>();
    k_decode<<<256, 512>>>(ctx, orig, maskp, out);
}

// round 5
// speedup vs baseline: 1.4843x; 1.2626x over previous
#include <cuda_runtime.h>
#include <stdint.h>
#include <math.h>

#define Bn 256
#define Nn 512
#define En 128
#define Hn 128
#define NEG_BIG (-100000000.0f)
#define TINY_F 1.17549435e-38f
#define FULLMASK 0xffffffffu

// out layout: [log_prob(256) | idxs(131072) | R(256) | start(512) | end(512)]
#define OUT_IDX   256
#define OUT_R     (OUT_IDX + Bn*Nn)
#define OUT_START (OUT_R + Bn)
#define OUT_END   (OUT_START + 2*Bn)

// ---------------- device scratch ----------------
__device__ float g_P[(size_t)Bn * Nn * Nn];       // 268 MB, P[b][j][n]
__device__ float g_ctxT[(size_t)Bn * En * Nn];    // 67 MB, ctxT[b][e][n]
__device__ float g_ctxVT[(size_t)Bn * Hn * Nn];   // 67 MB, (ctx@Wv_bot@Wq)^T [h][n]
__device__ float g_keysT[(size_t)Bn * Hn * Nn];   // 67 MB, keys^T [h][n]
__device__ float g_U[En * Hn];
__device__ float g_V[En * Hn];
__device__ float g_c0[Bn * Hn];
__device__ float g_q0[Bn * Hn];
__device__ float g_S0[Bn * Nn];
__device__ uint2 g_rng[Nn];

// ---------------- threefry2x32-20 (JAX-compatible) ----------------
__device__ __forceinline__ void tf2x32(uint32_t k0, uint32_t k1,
                                       uint32_t x0, uint32_t x1,
                                       uint32_t& y0, uint32_t& y1) {
    uint32_t k2 = k0 ^ k1 ^ 0x1BD11BDAu;
    x0 += k0; x1 += k1;
#define TF_RND(R) { x0 += x1; x1 = __funnelshift_l(x1, x1, (R)); x1 ^= x0; }
    TF_RND(13) TF_RND(15) TF_RND(26) TF_RND(6)   x0 += k1; x1 += k2 + 1u;
    TF_RND(17) TF_RND(29) TF_RND(16) TF_RND(24)  x0 += k2; x1 += k0 + 2u;
    TF_RND(13) TF_RND(15) TF_RND(26) TF_RND(6)   x0 += k0; x1 += k1 + 3u;
    TF_RND(17) TF_RND(29) TF_RND(16) TF_RND(24)  x0 += k1; x1 += k2 + 4u;
    TF_RND(13) TF_RND(15) TF_RND(26) TF_RND(6)   x0 += k2; x1 += k0 + 5u;
#undef TF_RND
    y0 = x0; y1 = x1;
}

__device__ __forceinline__ float gumbel_from(uint2 k, uint32_t c) {
    uint32_t y0, y1;
    tf2x32(k.x, k.y, 0u, c, y0, y1);
    uint32_t bits = y0 ^ y1;
    float f = __uint_as_float((bits >> 9) | 0x3f800000u) - 1.0f;
    float u = (f == 0.0f) ? TINY_F : f;
    return -logf(-logf(u));
}

// ---------------- cp.async helpers ----------------
__device__ __forceinline__ void cp16(void* sptr, const void* gptr) {
    uint32_t sa = (uint32_t)__cvta_generic_to_shared(sptr);
    asm volatile("cp.async.cg.shared.global [%0], [%1], 16;" :: "r"(sa), "l"(gptr));
}
#define CP_COMMIT() asm volatile("cp.async.commit_group;")
#define CP_WAIT1()  asm volatile("cp.async.wait_group 1;")
#define CP_WAIT0()  asm volatile("cp.async.wait_group 0;")

// ---------------- small precompute kernels ----------------
__global__ void k_rng() {
    int i = threadIdx.x;  // 512
    uint32_t y0, y1;
    tf2x32(0u, 42u, 0u, (uint32_t)i, y0, y1);
    g_rng[i] = make_uint2(y0, y1);
}

__global__ void k_uv(const float* __restrict__ W_v, const float* __restrict__ W_q) {
    int i = blockIdx.x;
    int h = threadIdx.x;
    float u = 0.f, v = 0.f;
    for (int j = 0; j < En; j++) {
        float wq = W_q[j * Hn + h];
        u += W_v[i * En + j] * wq;
        v += W_v[(En + i) * En + j] * wq;
    }
    g_U[i * Hn + h] = u;
    g_V[i * Hn + h] = v;
}

__global__ void k_rowconst(const float* __restrict__ ctx, const float* __restrict__ liw,
                           const float* __restrict__ W_h, const float* __restrict__ b_h,
                           const float* __restrict__ W_v, const float* __restrict__ b_v,
                           const float* __restrict__ W_q, const float* __restrict__ b_q) {
    __shared__ float mean_s[En];
    __shared__ float hbv[En];
    __shared__ float w0[En];
    int b = blockIdx.x, t = threadIdx.x;  // 128 threads
    double acc = 0.0;
    for (int n = 0; n < Nn; n++) acc += (double)ctx[((size_t)b * Nn + n) * En + t];
    mean_s[t] = (float)(acc * (1.0 / 512.0));
    float a2 = 0.f;
    for (int e2 = 0; e2 < 2 * En; e2++) a2 += liw[e2] * W_v[e2 * En + t];
    w0[t] = a2;
    __syncthreads();
    float hb = b_h[t];
    for (int e = 0; e < En; e++) hb += mean_s[e] * W_h[e * En + t];
    hbv[t] = hb + b_v[t];
    __syncthreads();
    float c0 = b_q[t], qw = 0.f;
    for (int e = 0; e < En; e++) {
        float wq = W_q[e * Hn + t];
        c0 += hbv[e] * wq;
        qw += w0[e] * wq;
    }
    g_c0[b * Hn + t] = c0;
    g_q0[b * Hn + t] = c0 + qw;
}

// transpose ctx[b][n][e] -> ctxT[b][e][n]
__global__ void k_tr(const float* __restrict__ ctx) {
    __shared__ float tile[32][33];
    int b = blockIdx.z;
    int e0 = blockIdx.x * 32;   // 4
    int n0 = blockIdx.y * 32;   // 16
    int tx = threadIdx.x, ty = threadIdx.y;  // 32 x 8
    for (int n = ty; n < 32; n += 8)
        tile[n][tx] = ctx[((size_t)b * Nn + n0 + n) * En + e0 + tx];
    __syncthreads();
    for (int e = ty; e < 32; e += 8)
        g_ctxT[((size_t)b * En + e0 + e) * Nn + n0 + tx] = tile[tx][e];
}

// ---------------- GEMM compute macro (8x8 per thread, 128x128 tile) ----------------
#define GEMM_COMPUTE(Ac, Bc)                                                   \
    _Pragma("unroll") for (int k = 0; k < 32; k++) {                           \
        float4 a0 = *(const float4*)&(Ac)[k * 128 + tr];                       \
        float4 a1 = *(const float4*)&(Ac)[k * 128 + tr + 4];                   \
        float4 b0 = *(const float4*)&(Bc)[k * 128 + tc];                       \
        float4 b1 = *(const float4*)&(Bc)[k * 128 + tc + 4];                   \
        float a[8] = {a0.x, a0.y, a0.z, a0.w, a1.x, a1.y, a1.z, a1.w};         \
        float bb[8] = {b0.x, b0.y, b0.z, b0.w, b1.x, b1.y, b1.z, b1.w};        \
        _Pragma("unroll") for (int i = 0; i < 8; i++)                          \
        _Pragma("unroll") for (int j = 0; j < 8; j++)                          \
            acc[i][j] += a[i] * bb[j];                                         \
    }

#define GEMM_ISSUE(ch, Ad, Bd, Asrc, AStr, Bsrc, BStr)                         \
    {                                                                          \
        const float* sa_ = (Asrc) + (size_t)(ch) * 32 * (AStr);                \
        const float* sb_ = (Bsrc) + (size_t)(ch) * 32 * (BStr);                \
        _Pragma("unroll") for (int s = 0; s < 4; s++) {                        \
            int f = t + 256 * s; int k = f >> 5; int c4 = (f & 31) * 4;        \
            cp16(&(Ad)[k * 128 + c4], &sa_[(size_t)k * (AStr) + c4]);          \
            cp16(&(Bd)[k * 128 + c4], &sb_[(size_t)k * (BStr) + c4]);          \
        }                                                                      \
        CP_COMMIT();                                                           \
    }

// NN: out_T[c][n] = sum_k ctxT[k][n] * Bm[k][c] (+bias). grid (4, 256, 2)
__global__ __launch_bounds__(256, 2)
void k_gemm_nn3(const float* __restrict__ B0, const float* __restrict__ B1,
                const float* __restrict__ bias1) {
    extern __shared__ float sm[];
    float* As0 = sm;           float* As1 = sm + 4096;
    float* Bs0 = sm + 8192;    float* Bs1 = sm + 12288;
    int rt = blockIdx.x, b = blockIdx.y, which = blockIdx.z;
    const float* Bm = which ? B1 : B0;
    const float* Ab = g_ctxT + (size_t)b * En * Nn + rt * 128;
    int t = threadIdx.x;
    int tr = (t >> 4) * 8, tc = (t & 15) * 8;
    float acc[8][8];
#pragma unroll
    for (int i = 0; i < 8; i++)
#pragma unroll
        for (int j = 0; j < 8; j++) acc[i][j] = 0.f;

    GEMM_ISSUE(0, As0, Bs0, Ab, Nn, Bm, Hn)
    GEMM_ISSUE(1, As1, Bs1, Ab, Nn, Bm, Hn)
    CP_WAIT1(); __syncthreads();
    GEMM_COMPUTE(As0, Bs0)
    __syncthreads();
    GEMM_ISSUE(2, As0, Bs0, Ab, Nn, Bm, Hn)
    CP_WAIT1(); __syncthreads();
    GEMM_COMPUTE(As1, Bs1)
    __syncthreads();
    GEMM_ISSUE(3, As1, Bs1, Ab, Nn, Bm, Hn)
    CP_WAIT1(); __syncthreads();
    GEMM_COMPUTE(As0, Bs0)
    CP_WAIT0(); __syncthreads();
    GEMM_COMPUTE(As1, Bs1)

    // store transposed: CT[c][rt*128 + r]
    float* CT = (which ? g_keysT : g_ctxVT) + (size_t)b * Hn * Nn + rt * 128;
#pragma unroll
    for (int j = 0; j < 8; j++) {
        int c = tc + j;
        float bia = which ? bias1[c] : 0.f;
        float4 v0 = make_float4(acc[0][j] + bia, acc[1][j] + bia,
                                acc[2][j] + bia, acc[3][j] + bia);
        float4 v1 = make_float4(acc[4][j] + bia, acc[5][j] + bia,
                                acc[6][j] + bia, acc[7][j] + bia);
        *(float4*)&CT[(size_t)c * Nn + tr]     = v0;
        *(float4*)&CT[(size_t)c * Nn + tr + 4] = v1;
    }
}

// NT: P[b][r][n] = scale * sum_h ctxVT[h][r] * keysT[h][n]. grid (4, 4, 256)
__global__ __launch_bounds__(256, 2)
void k_gemm_nt3() {
    extern __shared__ float sm[];
    float* As0 = sm;           float* As1 = sm + 4096;
    float* Bs0 = sm + 8192;    float* Bs1 = sm + 12288;
    int ct = blockIdx.x, rt = blockIdx.y, b = blockIdx.z;
    const float scale = 1.0f / sqrtf(128.0f);
    const float* Ab = g_ctxVT + (size_t)b * Hn * Nn + rt * 128;
    const float* Bb = g_keysT + (size_t)b * Hn * Nn + ct * 128;
    int t = threadIdx.x;
    int tr = (t >> 4) * 8, tc = (t & 15) * 8;
    float acc[8][8];
#pragma unroll
    for (int i = 0; i < 8; i++)
#pragma unroll
        for (int j = 0; j < 8; j++) acc[i][j] = 0.f;

    GEMM_ISSUE(0, As0, Bs0, Ab, Nn, Bb, Nn)
    GEMM_ISSUE(1, As1, Bs1, Ab, Nn, Bb, Nn)
    CP_WAIT1(); __syncthreads();
    GEMM_COMPUTE(As0, Bs0)
    __syncthreads();
    GEMM_ISSUE(2, As0, Bs0, Ab, Nn, Bb, Nn)
    CP_WAIT1(); __syncthreads();
    GEMM_COMPUTE(As1, Bs1)
    __syncthreads();
    GEMM_ISSUE(3, As1, Bs1, Ab, Nn, Bb, Nn)
    CP_WAIT1(); __syncthreads();
    GEMM_COMPUTE(As0, Bs0)
    CP_WAIT0(); __syncthreads();
    GEMM_COMPUTE(As1, Bs1)

    float* Cb = g_P + (size_t)b * Nn * Nn;
#pragma unroll
    for (int i = 0; i < 8; i++) {
        size_t row = (size_t)(rt * 128 + tr + i) * Nn + ct * 128 + tc;
        float4 v0 = make_float4(scale * acc[i][0], scale * acc[i][1],
                                scale * acc[i][2], scale * acc[i][3]);
        float4 v1 = make_float4(scale * acc[i][4], scale * acc[i][5],
                                scale * acc[i][6], scale * acc[i][7]);
        *(float4*)&Cb[row]     = v0;
        *(float4*)&Cb[row + 4] = v1;
    }
}

// S0[b][n] = scale * sum_h q0[b][h] * keysT[b][h][n]
__global__ void k_s0() {
    __shared__ float sq0[Hn];
    int b = blockIdx.x, n = threadIdx.x;  // 512
    if (n < Hn) sq0[n] = g_q0[b * Hn + n];
    __syncthreads();
    const float scale = 1.0f / sqrtf(128.0f);
    const float* KT = g_keysT + (size_t)b * Hn * Nn;
    float acc = 0.f;
#pragma unroll 8
    for (int h = 0; h < Hn; h++) acc += sq0[h] * KT[(size_t)h * Nn + n];
    g_S0[b * Nn + n] = scale * acc;
}

// ---------------- sequential decoder: 128 threads, 4 n/thread, 1 bar/step ----------------
__global__ __launch_bounds__(128, 8)
void k_decode(const float* __restrict__ ctx, const float* __restrict__ orig,
              const float* __restrict__ mask_in, float* __restrict__ out) {
    __shared__ uint2 sRng[Nn];
    __shared__ float sKey[2][4]; __shared__ int sIdx[2][4]; __shared__ float sE[2][4];
    __shared__ float sRow[En]; __shared__ float sCu[Hn];
    __shared__ float sLp[4];

    int b = blockIdx.x, t = threadIdx.x, w = t >> 5, l = t & 31;
    int n0 = t * 4;
    const float scale = 1.0f / sqrtf(128.0f);

    for (int f = t; f < Nn; f += 128) sRng[f] = g_rng[f];

    float4 s4 = *(const float4*)&g_S0[b * Nn + n0];
    float s[4] = {s4.x, s4.y, s4.z, s4.w};
    float4 m4 = *(const float4*)&mask_in[(size_t)b * Nn + n0];
    int maskbits = (m4.x > 0.f ? 1 : 0) | (m4.y > 0.f ? 2 : 0) |
                   (m4.z > 0.f ? 4 : 0) | (m4.w > 0.f ? 8 : 0);
    __syncthreads();
    float g[4], c0r[4] = {0.f, 0.f, 0.f, 0.f};
#pragma unroll
    for (int j = 0; j < 4; j++) g[j] = gumbel_from(sRng[0], (uint32_t)(b * Nn + n0 + j));

    float logp = 0.f, Racc = 0.f, px = 0.f, py = 0.f;
    const float* Pb = g_P + (size_t)b * Nn * Nn;

    for (int i = 0; i < Nn; i++) {
        float sp[4];
        float kk = -INFINITY; int kid = 0; float e = 0.f;
#pragma unroll
        for (int j = 0; j < 4; j++) {
            sp[j] = (maskbits >> j & 1) ? NEG_BIG : 10.0f * tanhf(s[j]);
            float key = sp[j] + g[j];
            if (key > kk) { kk = key; kid = n0 + j; }
            e += expf(sp[j]);
        }
#pragma unroll
        for (int off = 16; off; off >>= 1) {
            float k2 = __shfl_down_sync(FULLMASK, kk, off);
            int  i2 = __shfl_down_sync(FULLMASK, kid, off);
            float e2 = __shfl_down_sync(FULLMASK, e, off);
            if (k2 > kk) { kk = k2; kid = i2; }
            e += e2;
        }
        if (l == 0) { sKey[i & 1][w] = kk; sIdx[i & 1][w] = kid; sE[i & 1][w] = e; }
        __syncthreads();
        float kbest = sKey[i & 1][0]; int idx = sIdx[i & 1][0]; float E = sE[i & 1][0];
#pragma unroll
        for (int w2 = 1; w2 < 4; w2++) {
            float kw = sKey[i & 1][w2];
            if (kw > kbest) { kbest = kw; idx = sIdx[i & 1][w2]; }
            E += sE[i & 1][w2];
        }
        // dependent load first (critical path)
        float4 Pn = make_float4(0.f, 0.f, 0.f, 0.f);
        if (i + 1 < Nn) Pn = *(const float4*)&Pb[(size_t)idx * Nn + n0];
        // owner bookkeeping
        if ((idx >> 2) == t) {
            int jj = idx & 3;
            float spsel = (jj == 0) ? sp[0] : (jj == 1) ? sp[1] : (jj == 2) ? sp[2] : sp[3];
            logp += spsel - logf(E);
            maskbits |= 1 << jj;
        }
        if (t == 0) {
            out[OUT_IDX + b * Nn + i] = (float)idx;
            float ox = orig[((size_t)b * Nn + idx) * 2];
            float oy = orig[((size_t)b * Nn + idx) * 2 + 1];
            if (i > 0) { float dx = ox - px, dy = oy - py; Racc += sqrtf(dx * dx + dy * dy); }
            px = ox; py = oy;
            if (i == 0) { out[OUT_START + 2 * b] = ox; out[OUT_START + 2 * b + 1] = oy; }
            if (i == Nn - 1) {
                out[OUT_END + 2 * b] = ox; out[OUT_END + 2 * b + 1] = oy;
                out[OUT_R + b] = Racc;
            }
        }
        if (i == 0) {
            // cu = c0 + ctx[idx0] @ U ; c0r[n] = scale * cu . keysT[:,n]
            sRow[t] = ctx[((size_t)b * Nn + idx) * En + t];
            __syncthreads();
            float cu = g_c0[b * Hn + t];
            for (int e2 = 0; e2 < En; e2++) cu += sRow[e2] * g_U[e2 * Hn + t];
            sCu[t] = cu;
            __syncthreads();
            const float* KT = g_keysT + (size_t)b * Hn * Nn;
            float a0 = 0.f, a1 = 0.f, a2 = 0.f, a3 = 0.f;
#pragma unroll 8
            for (int h = 0; h < Hn; h++) {
                float cuh = sCu[h];
                float4 kv = *(const float4*)&KT[(size_t)h * Nn + n0];
                a0 += cuh * kv.x; a1 += cuh * kv.y; a2 += cuh * kv.z; a3 += cuh * kv.w;
            }
            c0r[0] = scale * a0; c0r[1] = scale * a1;
            c0r[2] = scale * a2; c0r[3] = scale * a3;
        }
        if (i + 1 < Nn) {
            uint2 rk = sRng[i + 1];
#pragma unroll
            for (int j = 0; j < 4; j++) g[j] = gumbel_from(rk, (uint32_t)(b * Nn + n0 + j));
            s[0] = c0r[0] + Pn.x; s[1] = c0r[1] + Pn.y;
            s[2] = c0r[2] + Pn.z; s[3] = c0r[3] + Pn.w;
        }
    }
    // final log_prob reduction (fixed order)
#pragma unroll
    for (int off = 16; off; off >>= 1) logp += __shfl_down_sync(FULLMASK, logp, off);
    if (l == 0) sLp[w] = logp;
    __syncthreads();
    if (t == 0) out[b] = ((sLp[0] + sLp[1]) + sLp[2]) + sLp[3];
}

// ---------------- launch ----------------
extern "C" void kernel_launch(void* const* d_in, const int* in_sizes, int n_in,
                              void* d_out, int out_size) {
    const float* ctx   = (const float*)d_in[0];
    const float* orig  = (const float*)d_in[1];
    const float* maskp = (const float*)d_in[2];
    const float* liw   = (const float*)d_in[3];
    const float* W_h   = (const float*)d_in[4];
    const float* b_h   = (const float*)d_in[5];
    const float* W_v   = (const float*)d_in[6];
    const float* b_v   = (const float*)d_in[7];
    const float* W_q   = (const float*)d_in[8];
    const float* b_q   = (const float*)d_in[9];
    const float* W_k   = (const float*)d_in[10];
    const float* b_k   = (const float*)d_in[11];
    float* out = (float*)d_out;

    void* pV;
    cudaGetSymbolAddress(&pV, g_V);

    const int GEMM_SMEM = 16384 * 4;  // 64 KB
    cudaFuncSetAttribute(k_gemm_nn3, cudaFuncAttributeMaxDynamicSharedMemorySize, GEMM_SMEM);
    cudaFuncSetAttribute(k_gemm_nt3, cudaFuncAttributeMaxDynamicSharedMemorySize, GEMM_SMEM);

    k_rng<<<1, 512>>>();
    k_uv<<<128, 128>>>(W_v, W_q);
    k_rowconst<<<256, 128>>>(ctx, liw, W_h, b_h, W_v, b_v, W_q, b_q);
    k_tr<<<dim3(4, 16, Bn), dim3(32, 8)>>>(ctx);
    k_gemm_nn3<<<dim3(4, Bn, 2), 256, GEMM_SMEM>>>((const float*)pV, W_k, b_k);
    k_gemm_nt3<<<dim3(4, 4, Bn), 256, GEMM_SMEM>>>();
    k_s0<<<256, 512>>>();
    k_decode<<<256, 128>>>(ctx, orig, maskp, out);
}

// round 7
// speedup vs baseline: 1.6295x; 1.0978x over previous
#include <cuda_runtime.h>
#include <stdint.h>
#include <math.h>

#define Bn 256
#define Nn 512
#define En 128
#define Hn 128
#define NEG_BIG (-100000000.0f)
#define TINY_F 1.17549435e-38f
#define FULLMASK 0xffffffffu

// out layout: [log_prob(256) | idxs(131072) | R(256) | start(512) | end(512)]
#define OUT_IDX   256
#define OUT_R     (OUT_IDX + Bn*Nn)
#define OUT_START (OUT_R + Bn)
#define OUT_END   (OUT_START + 2*Bn)

// ---------------- device scratch ----------------
__device__ float g_P[(size_t)Bn * Nn * Nn];       // 268 MB, P[b][j][n]
__device__ float g_ctxT[(size_t)Bn * En * Nn];    // 67 MB, ctxT[b][e][n]
__device__ float g_ctxVT[(size_t)Bn * Hn * Nn];   // 67 MB, (ctx@Wv_bot@Wq)^T [h][n]
__device__ float g_keysT[(size_t)Bn * Hn * Nn];   // 67 MB, keys^T [h][n]
__device__ float g_U[En * Hn];
__device__ float g_V[En * Hn];
__device__ float g_c0[Bn * Hn];
__device__ float g_q0[Bn * Hn];
__device__ float g_S0[Bn * Nn];
__device__ uint2 g_rng[Nn];

// ---------------- threefry2x32-20 (JAX-compatible) ----------------
__device__ __forceinline__ void tf2x32(uint32_t k0, uint32_t k1,
                                       uint32_t x0, uint32_t x1,
                                       uint32_t& y0, uint32_t& y1) {
    uint32_t k2 = k0 ^ k1 ^ 0x1BD11BDAu;
    x0 += k0; x1 += k1;
#define TF_RND(R) { x0 += x1; x1 = __funnelshift_l(x1, x1, (R)); x1 ^= x0; }
    TF_RND(13) TF_RND(15) TF_RND(26) TF_RND(6)   x0 += k1; x1 += k2 + 1u;
    TF_RND(17) TF_RND(29) TF_RND(16) TF_RND(24)  x0 += k2; x1 += k0 + 2u;
    TF_RND(13) TF_RND(15) TF_RND(26) TF_RND(6)   x0 += k0; x1 += k1 + 3u;
    TF_RND(17) TF_RND(29) TF_RND(16) TF_RND(24)  x0 += k1; x1 += k2 + 4u;
    TF_RND(13) TF_RND(15) TF_RND(26) TF_RND(6)   x0 += k2; x1 += k0 + 5u;
#undef TF_RND
    y0 = x0; y1 = x1;
}

__device__ __forceinline__ float gumbel_from(uint2 k, uint32_t c) {
    uint32_t y0, y1;
    tf2x32(k.x, k.y, 0u, c, y0, y1);
    uint32_t bits = y0 ^ y1;
    float f = __uint_as_float((bits >> 9) | 0x3f800000u) - 1.0f;
    float u = (f == 0.0f) ? TINY_F : f;
    return -logf(-logf(u));
}

// ---------------- cp.async helpers ----------------
__device__ __forceinline__ void cp16(void* sptr, const void* gptr) {
    uint32_t sa = (uint32_t)__cvta_generic_to_shared(sptr);
    asm volatile("cp.async.cg.shared.global [%0], [%1], 16;" :: "r"(sa), "l"(gptr));
}
#define CP_COMMIT() asm volatile("cp.async.commit_group;")
#define CP_WAIT1()  asm volatile("cp.async.wait_group 1;")
#define CP_WAIT0()  asm volatile("cp.async.wait_group 0;")

// ---------------- small precompute kernels ----------------
__global__ void k_rng() {
    int i = threadIdx.x;  // 512
    uint32_t y0, y1;
    tf2x32(0u, 42u, 0u, (uint32_t)i, y0, y1);
    g_rng[i] = make_uint2(y0, y1);
}

__global__ void k_uv(const float* __restrict__ W_v, const float* __restrict__ W_q) {
    int i = blockIdx.x;
    int h = threadIdx.x;
    float u = 0.f, v = 0.f;
    for (int j = 0; j < En; j++) {
        float wq = W_q[j * Hn + h];
        u += W_v[i * En + j] * wq;
        v += W_v[(En + i) * En + j] * wq;
    }
    g_U[i * Hn + h] = u;
    g_V[i * Hn + h] = v;
}

__global__ void k_rowconst(const float* __restrict__ ctx, const float* __restrict__ liw,
                           const float* __restrict__ W_h, const float* __restrict__ b_h,
                           const float* __restrict__ W_v, const float* __restrict__ b_v,
                           const float* __restrict__ W_q, const float* __restrict__ b_q) {
    __shared__ float mean_s[En];
    __shared__ float hbv[En];
    __shared__ float w0[En];
    int b = blockIdx.x, t = threadIdx.x;  // 128 threads
    double acc = 0.0;
    for (int n = 0; n < Nn; n++) acc += (double)ctx[((size_t)b * Nn + n) * En + t];
    mean_s[t] = (float)(acc * (1.0 / 512.0));
    float a2 = 0.f;
    for (int e2 = 0; e2 < 2 * En; e2++) a2 += liw[e2] * W_v[e2 * En + t];
    w0[t] = a2;
    __syncthreads();
    float hb = b_h[t];
    for (int e = 0; e < En; e++) hb += mean_s[e] * W_h[e * En + t];
    hbv[t] = hb + b_v[t];
    __syncthreads();
    float c0 = b_q[t], qw = 0.f;
    for (int e = 0; e < En; e++) {
        float wq = W_q[e * Hn + t];
        c0 += hbv[e] * wq;
        qw += w0[e] * wq;
    }
    g_c0[b * Hn + t] = c0;
    g_q0[b * Hn + t] = c0 + qw;
}

// transpose ctx[b][n][e] -> ctxT[b][e][n]
__global__ void k_tr(const float* __restrict__ ctx) {
    __shared__ float tile[32][33];
    int b = blockIdx.z;
    int e0 = blockIdx.x * 32;   // 4
    int n0 = blockIdx.y * 32;   // 16
    int tx = threadIdx.x, ty = threadIdx.y;  // 32 x 8
    for (int n = ty; n < 32; n += 8)
        tile[n][tx] = ctx[((size_t)b * Nn + n0 + n) * En + e0 + tx];
    __syncthreads();
    for (int e = ty; e < 32; e += 8)
        g_ctxT[((size_t)b * En + e0 + e) * Nn + n0 + tx] = tile[tx][e];
}

// ---------------- GEMM compute macro: 8x8 per thread, cols {tc4..tc4+3, 64+tc4..64+tc4+3}
// b-fragment loads are two float4 at 16B stride -> bank-conflict floor (2 phases).
#define GEMM_COMPUTE(Ac, Bc)                                                   \
    _Pragma("unroll") for (int k = 0; k < 32; k++) {                           \
        float4 a0 = *(const float4*)&(Ac)[k * 128 + tr];                       \
        float4 a1 = *(const float4*)&(Ac)[k * 128 + tr + 4];                   \
        float4 b0 = *(const float4*)&(Bc)[k * 128 + tc4];                      \
        float4 b1 = *(const float4*)&(Bc)[k * 128 + 64 + tc4];                 \
        float a[8] = {a0.x, a0.y, a0.z, a0.w, a1.x, a1.y, a1.z, a1.w};         \
        float bb[8] = {b0.x, b0.y, b0.z, b0.w, b1.x, b1.y, b1.z, b1.w};        \
        _Pragma("unroll") for (int i = 0; i < 8; i++)                          \
        _Pragma("unroll") for (int j = 0; j < 8; j++)                          \
            acc[i][j] += a[i] * bb[j];                                         \
    }

#define GEMM_ISSUE(ch, Ad, Bd, Asrc, AStr, Bsrc, BStr)                         \
    {                                                                          \
        const float* sa_ = (Asrc) + (size_t)(ch) * 32 * (AStr);                \
        const float* sb_ = (Bsrc) + (size_t)(ch) * 32 * (BStr);                \
        _Pragma("unroll") for (int s = 0; s < 4; s++) {                        \
            int f = t + 256 * s; int k = f >> 5; int c4 = (f & 31) * 4;        \
            cp16(&(Ad)[k * 128 + c4], &sa_[(size_t)k * (AStr) + c4]);          \
            cp16(&(Bd)[k * 128 + c4], &sb_[(size_t)k * (BStr) + c4]);          \
        }                                                                      \
        CP_COMMIT();                                                           \
    }

// NN: out_T[c][n] = sum_k ctxT[k][n] * Bm[k][c] (+bias). grid (4, 256, 2)
__global__ __launch_bounds__(256, 2)
void k_gemm_nn3(const float* __restrict__ B0, const float* __restrict__ B1,
                const float* __restrict__ bias1) {
    extern __shared__ float sm[];
    float* As0 = sm;           float* As1 = sm + 4096;
    float* Bs0 = sm + 8192;    float* Bs1 = sm + 12288;
    int rt = blockIdx.x, b = blockIdx.y, which = blockIdx.z;
    const float* Bm = which ? B1 : B0;
    const float* Ab = g_ctxT + (size_t)b * En * Nn + rt * 128;
    int t = threadIdx.x;
    int tr = (t >> 4) * 8, tc4 = (t & 15) * 4;
    float acc[8][8];
#pragma unroll
    for (int i = 0; i < 8; i++)
#pragma unroll
        for (int j = 0; j < 8; j++) acc[i][j] = 0.f;

    GEMM_ISSUE(0, As0, Bs0, Ab, Nn, Bm, Hn)
    GEMM_ISSUE(1, As1, Bs1, Ab, Nn, Bm, Hn)
    CP_WAIT1(); __syncthreads();
    GEMM_COMPUTE(As0, Bs0)
    __syncthreads();
    GEMM_ISSUE(2, As0, Bs0, Ab, Nn, Bm, Hn)
    CP_WAIT1(); __syncthreads();
    GEMM_COMPUTE(As1, Bs1)
    __syncthreads();
    GEMM_ISSUE(3, As1, Bs1, Ab, Nn, Bm, Hn)
    CP_WAIT1(); __syncthreads();
    GEMM_COMPUTE(As0, Bs0)
    CP_WAIT0(); __syncthreads();
    GEMM_COMPUTE(As1, Bs1)

    // store transposed: CT[c][rt*128 + r]; thread's cols: tc4+j (j<4), 64+tc4+j-4 (j>=4)
    float* CT = (which ? g_keysT : g_ctxVT) + (size_t)b * Hn * Nn + rt * 128;
#pragma unroll
    for (int j = 0; j < 8; j++) {
        int c = (j < 4) ? (tc4 + j) : (64 + tc4 + j - 4);
        float bia = which ? bias1[c] : 0.f;
        float4 v0 = make_float4(acc[0][j] + bia, acc[1][j] + bia,
                                acc[2][j] + bia, acc[3][j] + bia);
        float4 v1 = make_float4(acc[4][j] + bia, acc[5][j] + bia,
                                acc[6][j] + bia, acc[7][j] + bia);
        *(float4*)&CT[(size_t)c * Nn + tr]     = v0;
        *(float4*)&CT[(size_t)c * Nn + tr + 4] = v1;
    }
}

// NT: P[b][r][n] = scale * sum_h ctxVT[h][r] * keysT[h][n]. grid (4, 4, 256)
__global__ __launch_bounds__(256, 2)
void k_gemm_nt3() {
    extern __shared__ float sm[];
    float* As0 = sm;           float* As1 = sm + 4096;
    float* Bs0 = sm + 8192;    float* Bs1 = sm + 12288;
    int ct = blockIdx.x, rt = blockIdx.y, b = blockIdx.z;
    const float scale = 1.0f / sqrtf(128.0f);
    const float* Ab = g_ctxVT + (size_t)b * Hn * Nn + rt * 128;
    const float* Bb = g_keysT + (size_t)b * Hn * Nn + ct * 128;
    int t = threadIdx.x;
    int tr = (t >> 4) * 8, tc4 = (t & 15) * 4;
    float acc[8][8];
#pragma unroll
    for (int i = 0; i < 8; i++)
#pragma unroll
        for (int j = 0; j < 8; j++) acc[i][j] = 0.f;

    GEMM_ISSUE(0, As0, Bs0, Ab, Nn, Bb, Nn)
    GEMM_ISSUE(1, As1, Bs1, Ab, Nn, Bb, Nn)
    CP_WAIT1(); __syncthreads();
    GEMM_COMPUTE(As0, Bs0)
    __syncthreads();
    GEMM_ISSUE(2, As0, Bs0, Ab, Nn, Bb, Nn)
    CP_WAIT1(); __syncthreads();
    GEMM_COMPUTE(As1, Bs1)
    __syncthreads();
    GEMM_ISSUE(3, As1, Bs1, Ab, Nn, Bb, Nn)
    CP_WAIT1(); __syncthreads();
    GEMM_COMPUTE(As0, Bs0)
    CP_WAIT0(); __syncthreads();
    GEMM_COMPUTE(As1, Bs1)

    float* Cb = g_P + (size_t)b * Nn * Nn;
#pragma unroll
    for (int i = 0; i < 8; i++) {
        size_t row = (size_t)(rt * 128 + tr + i) * Nn + ct * 128;
        float4 v0 = make_float4(scale * acc[i][0], scale * acc[i][1],
                                scale * acc[i][2], scale * acc[i][3]);
        float4 v1 = make_float4(scale * acc[i][4], scale * acc[i][5],
                                scale * acc[i][6], scale * acc[i][7]);
        *(float4*)&Cb[row + tc4]      = v0;
        *(float4*)&Cb[row + 64 + tc4] = v1;
    }
}

// S0[b][n] = scale * sum_h q0[b][h] * keysT[b][h][n]
__global__ void k_s0() {
    __shared__ float sq0[Hn];
    int b = blockIdx.x, n = threadIdx.x;  // 512
    if (n < Hn) sq0[n] = g_q0[b * Hn + n];
    __syncthreads();
    const float scale = 1.0f / sqrtf(128.0f);
    const float* KT = g_keysT + (size_t)b * Hn * Nn;
    float acc = 0.f;
#pragma unroll 8
    for (int h = 0; h < Hn; h++) acc += sq0[h] * KT[(size_t)h * Nn + n];
    g_S0[b * Nn + n] = scale * acc;
}

// ---------------- sequential decoder ----------------
// 128 threads (4 warps), 4 n/thread, ONE barrier/step.
// Each warp speculatively cp.asyncs its LOCAL argmax candidate's P-row into smem;
// the global winner is always among the 4 candidates, so the dependent row is
// already in shared memory when the cross-warp resolution completes.
__global__ __launch_bounds__(128, 4)
void k_decode(const float* __restrict__ ctx, const float* __restrict__ orig,
              const float* __restrict__ mask_in, float* __restrict__ out) {
    __shared__ uint2 sRng[Nn];             // 4 KB
    __shared__ float sBuf[2][4][Nn];       // 16 KB: parity x warp x row
    __shared__ float sKey[2][4]; __shared__ int sIdx[2][4]; __shared__ float sE[2][4];
    __shared__ float sRow[En]; __shared__ float sCu[Hn];
    __shared__ float sLp[4];

    int b = blockIdx.x, t = threadIdx.x, w = t >> 5, l = t & 31;
    int n0 = t * 4;
    const float scale = 1.0f / sqrtf(128.0f);

    for (int f = t; f < Nn; f += 128) sRng[f] = g_rng[f];

    float4 s4 = *(const float4*)&g_S0[b * Nn + n0];
    float s[4] = {s4.x, s4.y, s4.z, s4.w};
    float4 m4 = *(const float4*)&mask_in[(size_t)b * Nn + n0];
    int maskbits = (m4.x > 0.f ? 1 : 0) | (m4.y > 0.f ? 2 : 0) |
                   (m4.z > 0.f ? 4 : 0) | (m4.w > 0.f ? 8 : 0);
    __syncthreads();
    float g[4], c0r[4] = {0.f, 0.f, 0.f, 0.f};
#pragma unroll
    for (int j = 0; j < 4; j++) g[j] = gumbel_from(sRng[0], (uint32_t)(b * Nn + n0 + j));

    float logp = 0.f, Racc = 0.f, px = 0.f, py = 0.f;
    const float* Pb = g_P + (size_t)b * Nn * Nn;

    for (int i = 0; i < Nn; i++) {
        int par = i & 1;
        // scores + thread-local argmax (first-index ties via strict >)
        float sp[4];
        float kk = -INFINITY; int kid = n0;
#pragma unroll
        for (int j = 0; j < 4; j++) {
            sp[j] = (maskbits >> j & 1) ? NEG_BIG : 10.0f * tanhf(s[j]);
            float key = sp[j] + g[j];
            if (key > kk) { kk = key; kid = n0 + j; }
        }
        // warp argmax via ordered-uint redux + ballot (lowest lane = lowest n on tie)
        uint32_t ub = __float_as_uint(kk);
        ub = (ub & 0x80000000u) ? ~ub : (ub | 0x80000000u);
        uint32_t um = __reduce_max_sync(FULLMASK, ub);
        uint32_t bal = __ballot_sync(FULLMASK, ub == um);
        int src = __ffs(bal) - 1;
        int kidw = __shfl_sync(FULLMASK, kid, src);
        float kkw = __shfl_sync(FULLMASK, kk, src);
        // speculative prefetch of this warp's candidate row (64 B per lane)
        if (i + 1 < Nn) {
            const float* srow = Pb + (size_t)kidw * Nn + l * 16;
            float* dst = &sBuf[par][w][l * 16];
            cp16(dst, srow); cp16(dst + 4, srow + 4);
            cp16(dst + 8, srow + 8); cp16(dst + 12, srow + 12);
        }
        CP_COMMIT();
        if (l == 0) { sKey[par][w] = kkw; sIdx[par][w] = kidw; }
        // off-critical-path: sum of exp (order matches previous rounds exactly)
        float e = 0.f;
#pragma unroll
        for (int j = 0; j < 4; j++) e += expf(sp[j]);
#pragma unroll
        for (int off = 16; off; off >>= 1) e += __shfl_down_sync(FULLMASK, e, off);
        if (l == 0) sE[par][w] = e;
        // gumbel for next step (independent of winner)
        if (i + 1 < Nn) {
            uint2 rk = sRng[i + 1];
#pragma unroll
            for (int j = 0; j < 4; j++) g[j] = gumbel_from(rk, (uint32_t)(b * Nn + n0 + j));
        }
        CP_WAIT0();
        __syncthreads();
        // cross-warp winner (ascending w, strict > -> lowest n on tie)
        float kbest = sKey[par][0]; int idx = sIdx[par][0]; int wstar = 0;
        float E = sE[par][0];
#pragma unroll
        for (int w2 = 1; w2 < 4; w2++) {
            float kw = sKey[par][w2];
            if (kw > kbest) { kbest = kw; idx = sIdx[par][w2]; wstar = w2; }
            E += sE[par][w2];
        }
        // owner bookkeeping
        if ((idx >> 2) == t) {
            int jj = idx & 3;
            float spsel = (jj == 0) ? sp[0] : (jj == 1) ? sp[1] : (jj == 2) ? sp[2] : sp[3];
            logp += spsel - logf(E);
            maskbits |= 1 << jj;
        }
        if (t == 0) {
            out[OUT_IDX + b * Nn + i] = (float)idx;
            float ox = orig[((size_t)b * Nn + idx) * 2];
            float oy = orig[((size_t)b * Nn + idx) * 2 + 1];
            if (i > 0) { float dx = ox - px, dy = oy - py; Racc += sqrtf(dx * dx + dy * dy); }
            px = ox; py = oy;
            if (i == 0) { out[OUT_START + 2 * b] = ox; out[OUT_START + 2 * b + 1] = oy; }
            if (i == Nn - 1) {
                out[OUT_END + 2 * b] = ox; out[OUT_END + 2 * b + 1] = oy;
                out[OUT_R + b] = Racc;
            }
        }
        if (i == 0) {
            // cu = c0 + ctx[idx0] @ U ; c0r[n] = scale * cu . keysT[:,n]
            sRow[t] = ctx[((size_t)b * Nn + idx) * En + t];
            __syncthreads();
            float cu = g_c0[b * Hn + t];
            for (int e2 = 0; e2 < En; e2++) cu += sRow[e2] * g_U[e2 * Hn + t];
            sCu[t] = cu;
            __syncthreads();
            const float* KT = g_keysT + (size_t)b * Hn * Nn;
            float a0 = 0.f, a1 = 0.f, a2 = 0.f, a3 = 0.f;
#pragma unroll 8
            for (int h = 0; h < Hn; h++) {
                float cuh = sCu[h];
                float4 kv = *(const float4*)&KT[(size_t)h * Nn + n0];
                a0 += cuh * kv.x; a1 += cuh * kv.y; a2 += cuh * kv.z; a3 += cuh * kv.w;
            }
            c0r[0] = scale * a0; c0r[1] = scale * a1;
            c0r[2] = scale * a2; c0r[3] = scale * a3;
        }
        if (i + 1 < Nn) {
            float4 Pn = *(const float4*)&sBuf[par][wstar][n0];
            s[0] = c0r[0] + Pn.x; s[1] = c0r[1] + Pn.y;
            s[2] = c0r[2] + Pn.z; s[3] = c0r[3] + Pn.w;
        }
    }
    // final log_prob reduction (fixed order)
#pragma unroll
    for (int off = 16; off; off >>= 1) logp += __shfl_down_sync(FULLMASK, logp, off);
    if (l == 0) sLp[w] = logp;
    __syncthreads();
    if (t == 0) out[b] = ((sLp[0] + sLp[1]) + sLp[2]) + sLp[3];
}

// ---------------- launch ----------------
extern "C" void kernel_launch(void* const* d_in, const int* in_sizes, int n_in,
                              void* d_out, int out_size) {
    const float* ctx   = (const float*)d_in[0];
    const float* orig  = (const float*)d_in[1];
    const float* maskp = (const float*)d_in[2];
    const float* liw   = (const float*)d_in[3];
    const float* W_h   = (const float*)d_in[4];
    const float* b_h   = (const float*)d_in[5];
    const float* W_v   = (const float*)d_in[6];
    const float* b_v   = (const float*)d_in[7];
    const float* W_q   = (const float*)d_in[8];
    const float* b_q   = (const float*)d_in[9];
    const float* W_k   = (const float*)d_in[10];
    const float* b_k   = (const float*)d_in[11];
    float* out = (float*)d_out;

    void* pV;
    cudaGetSymbolAddress(&pV, g_V);

    const int GEMM_SMEM = 16384 * 4;  // 64 KB
    cudaFuncSetAttribute(k_gemm_nn3, cudaFuncAttributeMaxDynamicSharedMemorySize, GEMM_SMEM);
    cudaFuncSetAttribute(k_gemm_nt3, cudaFuncAttributeMaxDynamicSharedMemorySize, GEMM_SMEM);

    k_rng<<<1, 512>>>();
    k_uv<<<128, 128>>>(W_v, W_q);
    k_rowconst<<<256, 128>>>(ctx, liw, W_h, b_h, W_v, b_v, W_q, b_q);
    k_tr<<<dim3(4, 16, Bn), dim3(32, 8)>>>(ctx);
    k_gemm_nn3<<<dim3(4, Bn, 2), 256, GEMM_SMEM>>>((const float*)pV, W_k, b_k);
    k_gemm_nt3<<<dim3(4, 4, Bn), 256, GEMM_SMEM>>>();
    k_s0<<<256, 512>>>();
    k_decode<<<256, 128>>>(ctx, orig, maskp, out);
}

// round 8
// speedup vs baseline: 1.8645x; 1.1442x over previous
#include <cuda_runtime.h>
#include <stdint.h>
#include <math.h>

#define Bn 256
#define Nn 512
#define En 128
#define Hn 128
#define NEG_BIG (-100000000.0f)
#define TINY_F 1.17549435e-38f
#define FULLMASK 0xffffffffu

// out layout: [log_prob(256) | idxs(131072) | R(256) | start(512) | end(512)]
#define OUT_IDX   256
#define OUT_R     (OUT_IDX + Bn*Nn)
#define OUT_START (OUT_R + Bn)
#define OUT_END   (OUT_START + 2*Bn)

// ---------------- device scratch ----------------
__device__ float g_P[(size_t)Bn * Nn * Nn];       // 268 MB, P[b][j][n]
__device__ float g_ctxT[(size_t)Bn * En * Nn];    // 67 MB, ctxT[b][e][n]
__device__ float g_ctxVT[(size_t)Bn * Hn * Nn];   // 67 MB, (ctx@Wv_bot@Wq)^T [h][n]
__device__ float g_keysT[(size_t)Bn * Hn * Nn];   // 67 MB, keys^T [h][n]
__device__ float g_U[En * Hn];
__device__ float g_V[En * Hn];
__device__ float g_c0[Bn * Hn];
__device__ float g_q0[Bn * Hn];
__device__ float g_S0[Bn * Nn];
__device__ uint2 g_rng[Nn];

// ---------------- threefry2x32-20 (JAX-compatible) ----------------
__device__ __forceinline__ void tf2x32(uint32_t k0, uint32_t k1,
                                       uint32_t x0, uint32_t x1,
                                       uint32_t& y0, uint32_t& y1) {
    uint32_t k2 = k0 ^ k1 ^ 0x1BD11BDAu;
    x0 += k0; x1 += k1;
#define TF_RND(R) { x0 += x1; x1 = __funnelshift_l(x1, x1, (R)); x1 ^= x0; }
    TF_RND(13) TF_RND(15) TF_RND(26) TF_RND(6)   x0 += k1; x1 += k2 + 1u;
    TF_RND(17) TF_RND(29) TF_RND(16) TF_RND(24)  x0 += k2; x1 += k0 + 2u;
    TF_RND(13) TF_RND(15) TF_RND(26) TF_RND(6)   x0 += k0; x1 += k1 + 3u;
    TF_RND(17) TF_RND(29) TF_RND(16) TF_RND(24)  x0 += k1; x1 += k2 + 4u;
    TF_RND(13) TF_RND(15) TF_RND(26) TF_RND(6)   x0 += k2; x1 += k0 + 5u;
#undef TF_RND
    y0 = x0; y1 = x1;
}

__device__ __forceinline__ float gumbel_from(uint2 k, uint32_t c) {
    uint32_t y0, y1;
    tf2x32(k.x, k.y, 0u, c, y0, y1);
    uint32_t bits = y0 ^ y1;
    float f = __uint_as_float((bits >> 9) | 0x3f800000u) - 1.0f;
    float u = (f == 0.0f) ? TINY_F : f;
    return -logf(-logf(u));
}

// ---------------- cp.async helpers ----------------
__device__ __forceinline__ void cp16(void* sptr, const void* gptr) {
    uint32_t sa = (uint32_t)__cvta_generic_to_shared(sptr);
    asm volatile("cp.async.cg.shared.global [%0], [%1], 16;" :: "r"(sa), "l"(gptr));
}
#define CP_COMMIT() asm volatile("cp.async.commit_group;")
#define CP_WAIT1()  asm volatile("cp.async.wait_group 1;")
#define CP_WAIT0()  asm volatile("cp.async.wait_group 0;")

// ---------------- packed f32x2 FMA (Blackwell; 2 fp32 FMAs per instruction) ----
__device__ __forceinline__ void ffma2(unsigned long long& d,
                                      unsigned long long a,
                                      unsigned long long b) {
    asm("fma.rn.f32x2 %0, %1, %2, %0;" : "+l"(d) : "l"(a), "l"(b));
}
__device__ __forceinline__ unsigned long long fpack2(float x) {
    unsigned long long r;
    asm("mov.b64 %0, {%1, %1};" : "=l"(r) : "f"(x));
    return r;
}

// ---------------- small precompute kernels ----------------
__global__ void k_rng() {
    int i = threadIdx.x;  // 512
    uint32_t y0, y1;
    tf2x32(0u, 42u, 0u, (uint32_t)i, y0, y1);
    g_rng[i] = make_uint2(y0, y1);
}

__global__ void k_uv(const float* __restrict__ W_v, const float* __restrict__ W_q) {
    int i = blockIdx.x;
    int h = threadIdx.x;
    float u = 0.f, v = 0.f;
    for (int j = 0; j < En; j++) {
        float wq = W_q[j * Hn + h];
        u += W_v[i * En + j] * wq;
        v += W_v[(En + i) * En + j] * wq;
    }
    g_U[i * Hn + h] = u;
    g_V[i * Hn + h] = v;
}

__global__ void k_rowconst(const float* __restrict__ ctx, const float* __restrict__ liw,
                           const float* __restrict__ W_h, const float* __restrict__ b_h,
                           const float* __restrict__ W_v, const float* __restrict__ b_v,
                           const float* __restrict__ W_q, const float* __restrict__ b_q) {
    __shared__ float mean_s[En];
    __shared__ float hbv[En];
    __shared__ float w0[En];
    int b = blockIdx.x, t = threadIdx.x;  // 128 threads
    double acc = 0.0;
    for (int n = 0; n < Nn; n++) acc += (double)ctx[((size_t)b * Nn + n) * En + t];
    mean_s[t] = (float)(acc * (1.0 / 512.0));
    float a2 = 0.f;
    for (int e2 = 0; e2 < 2 * En; e2++) a2 += liw[e2] * W_v[e2 * En + t];
    w0[t] = a2;
    __syncthreads();
    float hb = b_h[t];
    for (int e = 0; e < En; e++) hb += mean_s[e] * W_h[e * En + t];
    hbv[t] = hb + b_v[t];
    __syncthreads();
    float c0 = b_q[t], qw = 0.f;
    for (int e = 0; e < En; e++) {
        float wq = W_q[e * Hn + t];
        c0 += hbv[e] * wq;
        qw += w0[e] * wq;
    }
    g_c0[b * Hn + t] = c0;
    g_q0[b * Hn + t] = c0 + qw;
}

// transpose ctx[b][n][e] -> ctxT[b][e][n]
__global__ void k_tr(const float* __restrict__ ctx) {
    __shared__ float tile[32][33];
    int b = blockIdx.z;
    int e0 = blockIdx.x * 32;   // 4
    int n0 = blockIdx.y * 32;   // 16
    int tx = threadIdx.x, ty = threadIdx.y;  // 32 x 8
    for (int n = ty; n < 32; n += 8)
        tile[n][tx] = ctx[((size_t)b * Nn + n0 + n) * En + e0 + tx];
    __syncthreads();
    for (int e = ty; e < 32; e += 8)
        g_ctxT[((size_t)b * En + e0 + e) * Nn + n0 + tx] = tile[tx][e];
}

// ---------------- GEMM compute: 8x8 per thread via packed f32x2 FMA ----------
// Thread cols {tc4..tc4+3, 64+tc4..64+tc4+3}; b loads are 16B-aligned u64 pairs.
// acc2[i][p] = (C[i][2p], C[i][2p+1]); identical ops & k-order to scalar FFMA.
#define GEMM_COMPUTE(Ac, Bc)                                                   \
    _Pragma("unroll") for (int k = 0; k < 32; k++) {                           \
        float4 a0 = *(const float4*)&(Ac)[k * 128 + tr];                       \
        float4 a1 = *(const float4*)&(Ac)[k * 128 + tr + 4];                   \
        ulonglong2 bq0 = *(const ulonglong2*)&(Bc)[k * 128 + tc4];             \
        ulonglong2 bq1 = *(const ulonglong2*)&(Bc)[k * 128 + 64 + tc4];        \
        float a[8] = {a0.x, a0.y, a0.z, a0.w, a1.x, a1.y, a1.z, a1.w};         \
        _Pragma("unroll") for (int i = 0; i < 8; i++) {                        \
            unsigned long long ai = fpack2(a[i]);                              \
            ffma2(acc2[i][0], ai, bq0.x);                                      \
            ffma2(acc2[i][1], ai, bq0.y);                                      \
            ffma2(acc2[i][2], ai, bq1.x);                                      \
            ffma2(acc2[i][3], ai, bq1.y);                                      \
        }                                                                      \
    }

#define GEMM_ACC_DECL                                                          \
    unsigned long long acc2[8][4];                                             \
    _Pragma("unroll") for (int i = 0; i < 8; i++)                              \
    _Pragma("unroll") for (int p = 0; p < 4; p++) acc2[i][p] = 0ull;

#define GEMM_UNPACK                                                            \
    float acc[8][8];                                                           \
    _Pragma("unroll") for (int i = 0; i < 8; i++)                              \
    _Pragma("unroll") for (int p = 0; p < 4; p++) {                            \
        union { unsigned long long u; float2 f; } cv; cv.u = acc2[i][p];       \
        acc[i][2 * p] = cv.f.x; acc[i][2 * p + 1] = cv.f.y;                    \
    }

#define GEMM_ISSUE(ch, Ad, Bd, Asrc, AStr, Bsrc, BStr)                         \
    {                                                                          \
        const float* sa_ = (Asrc) + (size_t)(ch) * 32 * (AStr);                \
        const float* sb_ = (Bsrc) + (size_t)(ch) * 32 * (BStr);                \
        _Pragma("unroll") for (int s = 0; s < 4; s++) {                        \
            int f = t + 256 * s; int k = f >> 5; int c4 = (f & 31) * 4;        \
            cp16(&(Ad)[k * 128 + c4], &sa_[(size_t)k * (AStr) + c4]);          \
            cp16(&(Bd)[k * 128 + c4], &sb_[(size_t)k * (BStr) + c4]);          \
        }                                                                      \
        CP_COMMIT();                                                           \
    }

// NN: out_T[c][n] = sum_k ctxT[k][n] * Bm[k][c] (+bias). grid (4, 256, 2)
__global__ __launch_bounds__(256, 2)
void k_gemm_nn3(const float* __restrict__ B0, const float* __restrict__ B1,
                const float* __restrict__ bias1) {
    extern __shared__ float sm[];
    float* As0 = sm;           float* As1 = sm + 4096;
    float* Bs0 = sm + 8192;    float* Bs1 = sm + 12288;
    int rt = blockIdx.x, b = blockIdx.y, which = blockIdx.z;
    const float* Bm = which ? B1 : B0;
    const float* Ab = g_ctxT + (size_t)b * En * Nn + rt * 128;
    int t = threadIdx.x;
    int tr = (t >> 4) * 8, tc4 = (t & 15) * 4;
    GEMM_ACC_DECL

    GEMM_ISSUE(0, As0, Bs0, Ab, Nn, Bm, Hn)
    GEMM_ISSUE(1, As1, Bs1, Ab, Nn, Bm, Hn)
    CP_WAIT1(); __syncthreads();
    GEMM_COMPUTE(As0, Bs0)
    __syncthreads();
    GEMM_ISSUE(2, As0, Bs0, Ab, Nn, Bm, Hn)
    CP_WAIT1(); __syncthreads();
    GEMM_COMPUTE(As1, Bs1)
    __syncthreads();
    GEMM_ISSUE(3, As1, Bs1, Ab, Nn, Bm, Hn)
    CP_WAIT1(); __syncthreads();
    GEMM_COMPUTE(As0, Bs0)
    CP_WAIT0(); __syncthreads();
    GEMM_COMPUTE(As1, Bs1)
    GEMM_UNPACK

    // store transposed: CT[c][rt*128 + r]; thread's cols: tc4+j (j<4), 64+tc4+j-4 (j>=4)
    float* CT = (which ? g_keysT : g_ctxVT) + (size_t)b * Hn * Nn + rt * 128;
#pragma unroll
    for (int j = 0; j < 8; j++) {
        int c = (j < 4) ? (tc4 + j) : (64 + tc4 + j - 4);
        float bia = which ? bias1[c] : 0.f;
        float4 v0 = make_float4(acc[0][j] + bia, acc[1][j] + bia,
                                acc[2][j] + bia, acc[3][j] + bia);
        float4 v1 = make_float4(acc[4][j] + bia, acc[5][j] + bia,
                                acc[6][j] + bia, acc[7][j] + bia);
        *(float4*)&CT[(size_t)c * Nn + tr]     = v0;
        *(float4*)&CT[(size_t)c * Nn + tr + 4] = v1;
    }
}

// NT: P[b][r][n] = scale * sum_h ctxVT[h][r] * keysT[h][n]. grid (4, 4, 256)
__global__ __launch_bounds__(256, 2)
void k_gemm_nt3() {
    extern __shared__ float sm[];
    float* As0 = sm;           float* As1 = sm + 4096;
    float* Bs0 = sm + 8192;    float* Bs1 = sm + 12288;
    int ct = blockIdx.x, rt = blockIdx.y, b = blockIdx.z;
    const float scale = 1.0f / sqrtf(128.0f);
    const float* Ab = g_ctxVT + (size_t)b * Hn * Nn + rt * 128;
    const float* Bb = g_keysT + (size_t)b * Hn * Nn + ct * 128;
    int t = threadIdx.x;
    int tr = (t >> 4) * 8, tc4 = (t & 15) * 4;
    GEMM_ACC_DECL

    GEMM_ISSUE(0, As0, Bs0, Ab, Nn, Bb, Nn)
    GEMM_ISSUE(1, As1, Bs1, Ab, Nn, Bb, Nn)
    CP_WAIT1(); __syncthreads();
    GEMM_COMPUTE(As0, Bs0)
    __syncthreads();
    GEMM_ISSUE(2, As0, Bs0, Ab, Nn, Bb, Nn)
    CP_WAIT1(); __syncthreads();
    GEMM_COMPUTE(As1, Bs1)
    __syncthreads();
    GEMM_ISSUE(3, As1, Bs1, Ab, Nn, Bb, Nn)
    CP_WAIT1(); __syncthreads();
    GEMM_COMPUTE(As0, Bs0)
    CP_WAIT0(); __syncthreads();
    GEMM_COMPUTE(As1, Bs1)
    GEMM_UNPACK

    float* Cb = g_P + (size_t)b * Nn * Nn;
#pragma unroll
    for (int i = 0; i < 8; i++) {
        size_t row = (size_t)(rt * 128 + tr + i) * Nn + ct * 128;
        float4 v0 = make_float4(scale * acc[i][0], scale * acc[i][1],
                                scale * acc[i][2], scale * acc[i][3]);
        float4 v1 = make_float4(scale * acc[i][4], scale * acc[i][5],
                                scale * acc[i][6], scale * acc[i][7]);
        *(float4*)&Cb[row + tc4]      = v0;
        *(float4*)&Cb[row + 64 + tc4] = v1;
    }
}

// S0[b][n] = scale * sum_h q0[b][h] * keysT[b][h][n]
__global__ void k_s0() {
    __shared__ float sq0[Hn];
    int b = blockIdx.x, n = threadIdx.x;  // 512
    if (n < Hn) sq0[n] = g_q0[b * Hn + n];
    __syncthreads();
    const float scale = 1.0f / sqrtf(128.0f);
    const float* KT = g_keysT + (size_t)b * Hn * Nn;
    float acc = 0.f;
#pragma unroll 8
    for (int h = 0; h < Hn; h++) acc += sq0[h] * KT[(size_t)h * Nn + n];
    g_S0[b * Nn + n] = scale * acc;
}

// ---------------- sequential decoder ----------------
// 128 threads (4 warps), 4 n/thread, ONE barrier/step.
// Each warp speculatively cp.asyncs its LOCAL argmax candidate's P-row into smem;
// the global winner is always among the 4 candidates, so the dependent row is
// already in shared memory when the cross-warp resolution completes.
__global__ __launch_bounds__(128, 4)
void k_decode(const float* __restrict__ ctx, const float* __restrict__ orig,
              const float* __restrict__ mask_in, float* __restrict__ out) {
    __shared__ uint2 sRng[Nn];             // 4 KB
    __shared__ float sBuf[2][4][Nn];       // 16 KB: parity x warp x row
    __shared__ float sKey[2][4]; __shared__ int sIdx[2][4]; __shared__ float sE[2][4];
    __shared__ float sRow[En]; __shared__ float sCu[Hn];
    __shared__ float sLp[4];

    int b = blockIdx.x, t = threadIdx.x, w = t >> 5, l = t & 31;
    int n0 = t * 4;
    const float scale = 1.0f / sqrtf(128.0f);

    for (int f = t; f < Nn; f += 128) sRng[f] = g_rng[f];

    float4 s4 = *(const float4*)&g_S0[b * Nn + n0];
    float s[4] = {s4.x, s4.y, s4.z, s4.w};
    float4 m4 = *(const float4*)&mask_in[(size_t)b * Nn + n0];
    int maskbits = (m4.x > 0.f ? 1 : 0) | (m4.y > 0.f ? 2 : 0) |
                   (m4.z > 0.f ? 4 : 0) | (m4.w > 0.f ? 8 : 0);
    __syncthreads();
    float g[4], c0r[4] = {0.f, 0.f, 0.f, 0.f};
#pragma unroll
    for (int j = 0; j < 4; j++) g[j] = gumbel_from(sRng[0], (uint32_t)(b * Nn + n0 + j));

    float logp = 0.f, Racc = 0.f, px = 0.f, py = 0.f;
    const float* Pb = g_P + (size_t)b * Nn * Nn;

    for (int i = 0; i < Nn; i++) {
        int par = i & 1;
        // scores + thread-local argmax (first-index ties via strict >)
        float sp[4];
        float kk = -INFINITY; int kid = n0;
#pragma unroll
        for (int j = 0; j < 4; j++) {
            sp[j] = (maskbits >> j & 1) ? NEG_BIG : 10.0f * tanhf(s[j]);
            float key = sp[j] + g[j];
            if (key > kk) { kk = key; kid = n0 + j; }
        }
        // warp argmax via ordered-uint redux + ballot (lowest lane = lowest n on tie)
        uint32_t ub = __float_as_uint(kk);
        ub = (ub & 0x80000000u) ? ~ub : (ub | 0x80000000u);
        uint32_t um = __reduce_max_sync(FULLMASK, ub);
        uint32_t bal = __ballot_sync(FULLMASK, ub == um);
        int src = __ffs(bal) - 1;
        int kidw = __shfl_sync(FULLMASK, kid, src);
        float kkw = __shfl_sync(FULLMASK, kk, src);
        // speculative prefetch of this warp's candidate row (64 B per lane)
        if (i + 1 < Nn) {
            const float* srow = Pb + (size_t)kidw * Nn + l * 16;
            float* dst = &sBuf[par][w][l * 16];
            cp16(dst, srow); cp16(dst + 4, srow + 4);
            cp16(dst + 8, srow + 8); cp16(dst + 12, srow + 12);
        }
        CP_COMMIT();
        if (l == 0) { sKey[par][w] = kkw; sIdx[par][w] = kidw; }
        // off-critical-path: sum of exp (order matches previous rounds exactly)
        float e = 0.f;
#pragma unroll
        for (int j = 0; j < 4; j++) e += expf(sp[j]);
#pragma unroll
        for (int off = 16; off; off >>= 1) e += __shfl_down_sync(FULLMASK, e, off);
        if (l == 0) sE[par][w] = e;
        // gumbel for next step (independent of winner)
        if (i + 1 < Nn) {
            uint2 rk = sRng[i + 1];
#pragma unroll
            for (int j = 0; j < 4; j++) g[j] = gumbel_from(rk, (uint32_t)(b * Nn + n0 + j));
        }
        CP_WAIT0();
        __syncthreads();
        // cross-warp winner (ascending w, strict > -> lowest n on tie)
        float kbest = sKey[par][0]; int idx = sIdx[par][0]; int wstar = 0;
        float E = sE[par][0];
#pragma unroll
        for (int w2 = 1; w2 < 4; w2++) {
            float kw = sKey[par][w2];
            if (kw > kbest) { kbest = kw; idx = sIdx[par][w2]; wstar = w2; }
            E += sE[par][w2];
        }
        // owner bookkeeping
        if ((idx >> 2) == t) {
            int jj = idx & 3;
            float spsel = (jj == 0) ? sp[0] : (jj == 1) ? sp[1] : (jj == 2) ? sp[2] : sp[3];
            logp += spsel - logf(E);
            maskbits |= 1 << jj;
        }
        if (t == 0) {
            out[OUT_IDX + b * Nn + i] = (float)idx;
            float ox = orig[((size_t)b * Nn + idx) * 2];
            float oy = orig[((size_t)b * Nn + idx) * 2 + 1];
            if (i > 0) { float dx = ox - px, dy = oy - py; Racc += sqrtf(dx * dx + dy * dy); }
            px = ox; py = oy;
            if (i == 0) { out[OUT_START + 2 * b] = ox; out[OUT_START + 2 * b + 1] = oy; }
            if (i == Nn - 1) {
                out[OUT_END + 2 * b] = ox; out[OUT_END + 2 * b + 1] = oy;
                out[OUT_R + b] = Racc;
            }
        }
        if (i == 0) {
            // cu = c0 + ctx[idx0] @ U ; c0r[n] = scale * cu . keysT[:,n]
            sRow[t] = ctx[((size_t)b * Nn + idx) * En + t];
            __syncthreads();
            float cu = g_c0[b * Hn + t];
            for (int e2 = 0; e2 < En; e2++) cu += sRow[e2] * g_U[e2 * Hn + t];
            sCu[t] = cu;
            __syncthreads();
            const float* KT = g_keysT + (size_t)b * Hn * Nn;
            float a0 = 0.f, a1 = 0.f, a2 = 0.f, a3 = 0.f;
#pragma unroll 8
            for (int h = 0; h < Hn; h++) {
                float cuh = sCu[h];
                float4 kv = *(const float4*)&KT[(size_t)h * Nn + n0];
                a0 += cuh * kv.x; a1 += cuh * kv.y; a2 += cuh * kv.z; a3 += cuh * kv.w;
            }
            c0r[0] = scale * a0; c0r[1] = scale * a1;
            c0r[2] = scale * a2; c0r[3] = scale * a3;
        }
        if (i + 1 < Nn) {
            float4 Pn = *(const float4*)&sBuf[par][wstar][n0];
            s[0] = c0r[0] + Pn.x; s[1] = c0r[1] + Pn.y;
            s[2] = c0r[2] + Pn.z; s[3] = c0r[3] + Pn.w;
        }
    }
    // final log_prob reduction (fixed order)
#pragma unroll
    for (int off = 16; off; off >>= 1) logp += __shfl_down_sync(FULLMASK, logp, off);
    if (l == 0) sLp[w] = logp;
    __syncthreads();
    if (t == 0) out[b] = ((sLp[0] + sLp[1]) + sLp[2]) + sLp[3];
}

// ---------------- launch ----------------
extern "C" void kernel_launch(void* const* d_in, const int* in_sizes, int n_in,
                              void* d_out, int out_size) {
    const float* ctx   = (const float*)d_in[0];
    const float* orig  = (const float*)d_in[1];
    const float* maskp = (const float*)d_in[2];
    const float* liw   = (const float*)d_in[3];
    const float* W_h   = (const float*)d_in[4];
    const float* b_h   = (const float*)d_in[5];
    const float* W_v   = (const float*)d_in[6];
    const float* b_v   = (const float*)d_in[7];
    const float* W_q   = (const float*)d_in[8];
    const float* b_q   = (const float*)d_in[9];
    const float* W_k   = (const float*)d_in[10];
    const float* b_k   = (const float*)d_in[11];
    float* out = (float*)d_out;

    void* pV;
    cudaGetSymbolAddress(&pV, g_V);

    const int GEMM_SMEM = 16384 * 4;  // 64 KB
    cudaFuncSetAttribute(k_gemm_nn3, cudaFuncAttributeMaxDynamicSharedMemorySize, GEMM_SMEM);
    cudaFuncSetAttribute(k_gemm_nt3, cudaFuncAttributeMaxDynamicSharedMemorySize, GEMM_SMEM);

    k_rng<<<1, 512>>>();
    k_uv<<<128, 128>>>(W_v, W_q);
    k_rowconst<<<256, 128>>>(ctx, liw, W_h, b_h, W_v, b_v, W_q, b_q);
    k_tr<<<dim3(4, 16, Bn), dim3(32, 8)>>>(ctx);
    k_gemm_nn3<<<dim3(4, Bn, 2), 256, GEMM_SMEM>>>((const float*)pV, W_k, b_k);
    k_gemm_nt3<<<dim3(4, 4, Bn), 256, GEMM_SMEM>>>();
    k_s0<<<256, 512>>>();
    k_decode<<<256, 128>>>(ctx, orig, maskp, out);
}